// round 8
// baseline (speedup 1.0000x reference)
#include <cuda_runtime.h>
#include <math.h>
#include <stdint.h>

#define TOK    1568
#define BATCH  4
#define CDIM   768
#define TTOK   (BATCH*TOK)
#define QKVDIM 2304
#define HID    3072
#define NHEAD  12
#define DHEAD  64

__device__ float g_t[TTOK * CDIM];
__device__ float g_h[TTOK * CDIM];
__device__ float g_qkv[TTOK * QKVDIM];
__device__ float g_o[TTOK * CDIM];
__device__ float g_mlp[TTOK * HID];

// ---------------- ptx helpers ----------------
__device__ __forceinline__ void mma_tf32(float* d, const uint32_t* a, const uint32_t* b) {
    asm volatile(
        "mma.sync.aligned.m16n8k8.row.col.f32.tf32.tf32.f32 "
        "{%0,%1,%2,%3}, {%4,%5,%6,%7}, {%8,%9}, {%0,%1,%2,%3};"
        : "+f"(d[0]), "+f"(d[1]), "+f"(d[2]), "+f"(d[3])
        : "r"(a[0]), "r"(a[1]), "r"(a[2]), "r"(a[3]), "r"(b[0]), "r"(b[1]));
}
__device__ __forceinline__ void cp16(uint32_t dst, const void* src) {
    asm volatile("cp.async.cg.shared.global [%0], [%1], 16;" :: "r"(dst), "l"(src));
}
__device__ __forceinline__ void cp_commit() { asm volatile("cp.async.commit_group;"); }
template <int N> __device__ __forceinline__ void cp_wait() {
    asm volatile("cp.async.wait_group %0;" :: "n"(N));
}
__device__ __forceinline__ float gelu_exact(float v) {
    return 0.5f * v * (1.f + erff(v * 0.70710678118654752f));
}

// ---------------- conv + bias + residual + tokenize ----------------
__global__ void conv_pos_kernel(const float* __restrict__ x,
                                const float* __restrict__ pw,
                                const float* __restrict__ pb) {
    int bc = blockIdx.x;
    int c  = bc % CDIM;
    int b  = bc / CDIM;
    __shared__ float sx[TOK];
    __shared__ float sw[27];
    int tid = threadIdx.x;
    const float* xs = x + (size_t)bc * TOK;
    for (int i = tid; i < TOK; i += 256) sx[i] = xs[i];
    if (tid < 27) sw[tid] = pw[c * 27 + tid];
    __syncthreads();
    float pbv = pb[c];
    for (int idx = tid; idx < TOK; idx += 256) {
        int d = idx / 196; int r = idx - d * 196;
        int h = r / 14;    int w = r - h * 14;
        float acc = 0.f;
        #pragma unroll
        for (int kd = 0; kd < 3; kd++) {
            int dd = d + kd - 1;
            if (dd < 0 || dd >= 8) continue;
            #pragma unroll
            for (int kh = 0; kh < 3; kh++) {
                int hh = h + kh - 1;
                if (hh < 0 || hh >= 14) continue;
                #pragma unroll
                for (int kw = 0; kw < 3; kw++) {
                    int ww = w + kw - 1;
                    if (ww < 0 || ww >= 14) continue;
                    acc += sw[kd * 9 + kh * 3 + kw] * sx[dd * 196 + hh * 14 + ww];
                }
            }
        }
        g_t[(size_t)(b * TOK + idx) * CDIM + c] = sx[idx] + acc + pbv;
    }
}

// ---------------- LayerNorm ----------------
__global__ void ln_kernel(const float* __restrict__ in, const float* __restrict__ w,
                          const float* __restrict__ bsrc, float* __restrict__ out) {
    int t = blockIdx.x;
    int tid = threadIdx.x;
    const float* row = in + (size_t)t * CDIM;
    float v0 = row[tid], v1 = row[tid + 256], v2 = row[tid + 512];
    float s  = v0 + v1 + v2;
    float sq = v0 * v0 + v1 * v1 + v2 * v2;
    #pragma unroll
    for (int off = 16; off; off >>= 1) {
        s  += __shfl_xor_sync(0xffffffffu, s,  off);
        sq += __shfl_xor_sync(0xffffffffu, sq, off);
    }
    __shared__ float ss[8], ssq[8];
    int wid = tid >> 5, lid = tid & 31;
    if (lid == 0) { ss[wid] = s; ssq[wid] = sq; }
    __syncthreads();
    if (tid < 32) {
        s  = (lid < 8) ? ss[lid]  : 0.f;
        sq = (lid < 8) ? ssq[lid] : 0.f;
        #pragma unroll
        for (int off = 4; off; off >>= 1) {
            s  += __shfl_xor_sync(0xffffffffu, s,  off);
            sq += __shfl_xor_sync(0xffffffffu, sq, off);
        }
        if (lid == 0) { ss[0] = s; ssq[0] = sq; }
    }
    __syncthreads();
    float mean = ss[0] * (1.f / CDIM);
    float var  = ssq[0] * (1.f / CDIM) - mean * mean;
    float rs   = rsqrtf(var + 1e-5f);
    float* orow = out + (size_t)t * CDIM;
    orow[tid]       = (v0 - mean) * rs * w[tid]       + bsrc[tid];
    orow[tid + 256] = (v1 - mean) * rs * w[tid + 256] + bsrc[tid + 256];
    orow[tid + 512] = (v2 - mean) * rs * w[tid + 512] + bsrc[tid + 512];
}

// ---------------- tf32 mma.sync GEMM: 64x64 warp tiles, 3-stage cp.async ----------------
// C[M,N] = A[M,K] @ B[N,K]^T. Block 128x128, 128 thr (4 warps), warp tile 64x64.
// LDS/mma = 1.0 (was 1.5). Row-major smem stride 20; 1 barrier per BK=16 chunk.
#define G_STRIDE 20
#define G_MATF   (128 * G_STRIDE)          // 2560 floats
#define G_STAGEF (2 * G_MATF)              // 5120 floats
#define GSMEM_B  (3 * G_STAGEF * 4)        // 61440 bytes

template <int MODE>
__global__ void __launch_bounds__(128, 2)
gemm_tc(const float* __restrict__ A, const float* __restrict__ B,
        const float* __restrict__ bias, const float* __restrict__ resid,
        float* __restrict__ C, int N, int K) {
    extern __shared__ __align__(16) float sm[];
    int tid = threadIdx.x;
    int lane = tid & 31, warp = tid >> 5;
    int wm = warp >> 1, wn = warp & 1;
    int m0 = blockIdx.y << 7, n0 = blockIdx.x << 7;

    // loader: one 16-float row per thread (4+4 cp16)
    const float* Ag = A + (size_t)(m0 + tid) * K;
    const float* Bg = B + (size_t)(n0 + tid) * K;
    uint32_t sa0 = (uint32_t)__cvta_generic_to_shared(sm) + tid * G_STRIDE * 4;
    uint32_t sb0 = sa0 + G_MATF * 4;

    int nch = K >> 4;
    auto load_chunk = [&](int ch) {
        uint32_t d = (uint32_t)(ch % 3) * (G_STAGEF * 4);
        int off = ch << 4;
        #pragma unroll
        for (int g = 0; g < 4; g++) {
            cp16(sa0 + d + g * 16, Ag + off + g * 4);
            cp16(sb0 + d + g * 16, Bg + off + g * 4);
        }
        cp_commit();
    };

    float acc[4][8][4];
    #pragma unroll
    for (int mi = 0; mi < 4; mi++)
        #pragma unroll
        for (int ni = 0; ni < 8; ni++)
            #pragma unroll
            for (int r = 0; r < 4; r++) acc[mi][ni][r] = 0.f;

    int mbase = wm * 64 + (lane >> 2);
    int nbase = wn * 64 + (lane >> 2);
    int kq = lane & 3;

    load_chunk(0);
    load_chunk(1);
    for (int ch = 0; ch < nch; ch++) {
        if (ch < nch - 1) cp_wait<1>(); else cp_wait<0>();
        __syncthreads();
        if (ch + 2 < nch) load_chunk(ch + 2);
        const float* as = sm + (ch % 3) * G_STAGEF;
        const float* bs = as + G_MATF;
        #pragma unroll
        for (int kb = 0; kb < 16; kb += 8) {
            int kk = kb + kq;
            uint32_t af[4][4], bf[8][2];
            #pragma unroll
            for (int mi = 0; mi < 4; mi++) {
                int m = mbase + mi * 16;
                af[mi][0] = __float_as_uint(as[m * G_STRIDE + kk]);
                af[mi][1] = __float_as_uint(as[(m + 8) * G_STRIDE + kk]);
                af[mi][2] = __float_as_uint(as[m * G_STRIDE + kk + 4]);
                af[mi][3] = __float_as_uint(as[(m + 8) * G_STRIDE + kk + 4]);
            }
            #pragma unroll
            for (int ni = 0; ni < 8; ni++) {
                int n = nbase + ni * 8;
                bf[ni][0] = __float_as_uint(bs[n * G_STRIDE + kk]);
                bf[ni][1] = __float_as_uint(bs[n * G_STRIDE + kk + 4]);
            }
            #pragma unroll
            for (int mi = 0; mi < 4; mi++)
                #pragma unroll
                for (int ni = 0; ni < 8; ni++)
                    mma_tf32(acc[mi][ni], af[mi], bf[ni]);
        }
    }

    // epilogue
    int r0 = lane >> 2, cq = (lane & 3) * 2;
    #pragma unroll
    for (int mi = 0; mi < 4; mi++) {
        int rowA = m0 + wm * 64 + mi * 16 + r0;
        int rowB = rowA + 8;
        #pragma unroll
        for (int ni = 0; ni < 8; ni++) {
            int col = n0 + wn * 64 + ni * 8 + cq;
            float2 va = make_float2(acc[mi][ni][0], acc[mi][ni][1]);
            float2 vb = make_float2(acc[mi][ni][2], acc[mi][ni][3]);
            if (MODE == 1) {
                float2 bv = *(const float2*)(bias + col);
                float2 ra = *(const float2*)(resid + (size_t)rowA * N + col);
                float2 rb = *(const float2*)(resid + (size_t)rowB * N + col);
                va.x += bv.x + ra.x; va.y += bv.y + ra.y;
                vb.x += bv.x + rb.x; vb.y += bv.y + rb.y;
            } else if (MODE == 2) {
                float2 bv = *(const float2*)(bias + col);
                va.x = gelu_exact(va.x + bv.x); va.y = gelu_exact(va.y + bv.y);
                vb.x = gelu_exact(vb.x + bv.x); vb.y = gelu_exact(vb.y + bv.y);
            }
            *(float2*)(C + (size_t)rowA * N + col) = va;
            *(float2*)(C + (size_t)rowB * N + col) = vb;
        }
    }
}

// ---------------- tf32 flash attention (proven R4 version) ----------------
__global__ void __launch_bounds__(128)
attn_tc(const float* __restrict__ qkv, float* __restrict__ o) {
    __shared__ __align__(16) float KP[64 * 68];
    __shared__ __align__(16) float Vs[64 * 72];
    int tid = threadIdx.x, lane = tid & 31, warp = tid >> 5;
    int bh = blockIdx.y;
    int b = bh / NHEAD, h = bh % NHEAD;
    int q0 = blockIdx.x * 64;
    const float* base = qkv + (size_t)b * TOK * QKVDIM + h * DHEAD;

    int r0 = lane >> 2, kq = lane & 3;
    uint32_t qf[8][4];
    {
        int qa = q0 + warp * 16 + r0;
        int qb = qa + 8;
        const float* pa = base + (size_t)qa * QKVDIM;
        const float* pb = base + (size_t)qb * QKVDIM;
        bool va = qa < TOK, vb = qb < TOK;
        #pragma unroll
        for (int kt = 0; kt < 8; kt++) {
            int k = kt * 8 + kq;
            qf[kt][0] = va ? __float_as_uint(pa[k] * 0.125f) : 0u;
            qf[kt][1] = vb ? __float_as_uint(pb[k] * 0.125f) : 0u;
            qf[kt][2] = va ? __float_as_uint(pa[k + 4] * 0.125f) : 0u;
            qf[kt][3] = vb ? __float_as_uint(pb[k + 4] * 0.125f) : 0u;
        }
    }

    float oacc[8][4];
    #pragma unroll
    for (int nt = 0; nt < 8; nt++)
        #pragma unroll
        for (int rr = 0; rr < 4; rr++) oacc[nt][rr] = 0.f;
    float mi0 = -1e30f, mi1 = -1e30f, li0 = 0.f, li1 = 0.f;

    for (int kc = 0; kc < 25; kc++) {
        __syncthreads();
        #pragma unroll
        for (int i = 0; i < 8; i++) {
            int q = tid + i * 128;
            int key = q >> 4;
            int d4  = (q & 15) << 2;
            int kg = kc * 64 + key;
            float4 kv = make_float4(0.f, 0.f, 0.f, 0.f);
            float4 vv = make_float4(0.f, 0.f, 0.f, 0.f);
            if (kg < TOK) {
                kv = *(const float4*)(base + (size_t)kg * QKVDIM + CDIM + d4);
                vv = *(const float4*)(base + (size_t)kg * QKVDIM + 2 * CDIM + d4);
            }
            *(float4*)&KP[key * 68 + d4] = kv;
            *(float4*)&Vs[key * 72 + d4] = vv;
        }
        __syncthreads();

        float s[8][4];
        #pragma unroll
        for (int ni = 0; ni < 8; ni++)
            #pragma unroll
            for (int rr = 0; rr < 4; rr++) s[ni][rr] = 0.f;
        #pragma unroll
        for (int kt = 0; kt < 8; kt++) {
            int kk = kt * 8 + kq;
            #pragma unroll
            for (int ni = 0; ni < 8; ni++) {
                int n = ni * 8 + r0;
                uint32_t bf[2];
                bf[0] = __float_as_uint(KP[n * 68 + kk]);
                bf[1] = __float_as_uint(KP[n * 68 + kk + 4]);
                mma_tf32(s[ni], qf[kt], bf);
            }
        }
        if (kc == 24) {
            #pragma unroll
            for (int ni = 0; ni < 8; ni++) {
                int c = kc * 64 + ni * 8 + kq * 2;
                if (c >= TOK)     { s[ni][0] = -1e30f; s[ni][2] = -1e30f; }
                if (c + 1 >= TOK) { s[ni][1] = -1e30f; s[ni][3] = -1e30f; }
            }
        }
        float mr0 = -1e30f, mr1 = -1e30f;
        #pragma unroll
        for (int ni = 0; ni < 8; ni++) {
            mr0 = fmaxf(mr0, fmaxf(s[ni][0], s[ni][1]));
            mr1 = fmaxf(mr1, fmaxf(s[ni][2], s[ni][3]));
        }
        mr0 = fmaxf(mr0, __shfl_xor_sync(0xffffffffu, mr0, 1));
        mr0 = fmaxf(mr0, __shfl_xor_sync(0xffffffffu, mr0, 2));
        mr1 = fmaxf(mr1, __shfl_xor_sync(0xffffffffu, mr1, 1));
        mr1 = fmaxf(mr1, __shfl_xor_sync(0xffffffffu, mr1, 2));
        float mn0 = fmaxf(mi0, mr0), mn1 = fmaxf(mi1, mr1);
        float a0 = __expf(mi0 - mn0), a1 = __expf(mi1 - mn1);
        float sum0 = 0.f, sum1 = 0.f;
        #pragma unroll
        for (int ni = 0; ni < 8; ni++) {
            s[ni][0] = __expf(s[ni][0] - mn0);
            s[ni][1] = __expf(s[ni][1] - mn0);
            s[ni][2] = __expf(s[ni][2] - mn1);
            s[ni][3] = __expf(s[ni][3] - mn1);
            sum0 += s[ni][0] + s[ni][1];
            sum1 += s[ni][2] + s[ni][3];
        }
        sum0 += __shfl_xor_sync(0xffffffffu, sum0, 1);
        sum0 += __shfl_xor_sync(0xffffffffu, sum0, 2);
        sum1 += __shfl_xor_sync(0xffffffffu, sum1, 1);
        sum1 += __shfl_xor_sync(0xffffffffu, sum1, 2);
        li0 = li0 * a0 + sum0; li1 = li1 * a1 + sum1;
        mi0 = mn0; mi1 = mn1;
        #pragma unroll
        for (int nt = 0; nt < 8; nt++) {
            oacc[nt][0] *= a0; oacc[nt][1] *= a0;
            oacc[nt][2] *= a1; oacc[nt][3] *= a1;
        }
        __syncthreads();
        {
            int prow = warp * 16 + r0;
            #pragma unroll
            for (int ni = 0; ni < 8; ni++) {
                int col = ni * 8 + kq * 2;
                *(float2*)&KP[prow * 68 + col]       = make_float2(s[ni][0], s[ni][1]);
                *(float2*)&KP[(prow + 8) * 68 + col] = make_float2(s[ni][2], s[ni][3]);
            }
        }
        __syncwarp();
        #pragma unroll
        for (int kt = 0; kt < 8; kt++) {
            int kk = kt * 8 + kq;
            uint32_t pf[4];
            int prow = warp * 16 + r0;
            pf[0] = __float_as_uint(KP[prow * 68 + kk]);
            pf[1] = __float_as_uint(KP[(prow + 8) * 68 + kk]);
            pf[2] = __float_as_uint(KP[prow * 68 + kk + 4]);
            pf[3] = __float_as_uint(KP[(prow + 8) * 68 + kk + 4]);
            #pragma unroll
            for (int nt = 0; nt < 8; nt++) {
                int n = nt * 8 + r0;
                uint32_t bf[2];
                bf[0] = __float_as_uint(Vs[kk * 72 + n]);
                bf[1] = __float_as_uint(Vs[(kk + 4) * 72 + n]);
                mma_tf32(oacc[nt], pf, bf);
            }
        }
    }

    int qa = q0 + warp * 16 + r0;
    int qb = qa + 8;
    float inv0 = 1.f / li0, inv1 = 1.f / li1;
    #pragma unroll
    for (int nt = 0; nt < 8; nt++) {
        int col = h * DHEAD + nt * 8 + kq * 2;
        if (qa < TOK)
            *(float2*)(o + (size_t)(b * TOK + qa) * CDIM + col) =
                make_float2(oacc[nt][0] * inv0, oacc[nt][1] * inv0);
        if (qb < TOK)
            *(float2*)(o + (size_t)(b * TOK + qb) * CDIM + col) =
                make_float2(oacc[nt][2] * inv1, oacc[nt][3] * inv1);
    }
}

// ---------------- untokenize ----------------
__global__ void untok_kernel(float* __restrict__ out) {
    __shared__ float tile[32][33];
    int b  = blockIdx.z;
    int s0 = blockIdx.x * 32;
    int c0 = blockIdx.y * 32;
    int tx = threadIdx.x, ty = threadIdx.y;
    #pragma unroll
    for (int r = ty; r < 32; r += 8)
        tile[r][tx] = g_t[(size_t)(b * TOK + s0 + r) * CDIM + c0 + tx];
    __syncthreads();
    #pragma unroll
    for (int r = ty; r < 32; r += 8)
        out[(size_t)(b * CDIM + c0 + r) * TOK + s0 + tx] = tile[tx][r];
}

// ---------------- launch ----------------
extern "C" void kernel_launch(void* const* d_in, const int* in_sizes, int n_in,
                              void* d_out, int out_size) {
    const float* x      = (const float*)d_in[0];
    const float* pos_w  = (const float*)d_in[1];
    const float* pos_b  = (const float*)d_in[2];
    const float* ln1_w  = (const float*)d_in[3];
    const float* ln1_b  = (const float*)d_in[4];
    const float* qkv_w  = (const float*)d_in[5];
    const float* proj_w = (const float*)d_in[6];
    const float* proj_b = (const float*)d_in[7];
    const float* ln2_w  = (const float*)d_in[8];
    const float* ln2_b  = (const float*)d_in[9];
    const float* fc1_w  = (const float*)d_in[10];
    const float* fc1_b  = (const float*)d_in[11];
    const float* fc2_w  = (const float*)d_in[12];
    const float* fc2_b  = (const float*)d_in[13];
    float* out = (float*)d_out;

    float *t, *hbuf, *qkvb, *ob, *mlpb;
    cudaGetSymbolAddress((void**)&t,    g_t);
    cudaGetSymbolAddress((void**)&hbuf, g_h);
    cudaGetSymbolAddress((void**)&qkvb, g_qkv);
    cudaGetSymbolAddress((void**)&ob,   g_o);
    cudaGetSymbolAddress((void**)&mlpb, g_mlp);

    cudaFuncSetAttribute(gemm_tc<0>, cudaFuncAttributeMaxDynamicSharedMemorySize, GSMEM_B);
    cudaFuncSetAttribute(gemm_tc<1>, cudaFuncAttributeMaxDynamicSharedMemorySize, GSMEM_B);
    cudaFuncSetAttribute(gemm_tc<2>, cudaFuncAttributeMaxDynamicSharedMemorySize, GSMEM_B);

    conv_pos_kernel<<<BATCH * CDIM, 256>>>(x, pos_w, pos_b);
    ln_kernel<<<TTOK, 256>>>(t, ln1_w, ln1_b, hbuf);
    gemm_tc<0><<<dim3(QKVDIM / 128, TTOK / 128), 128, GSMEM_B>>>(hbuf, qkv_w, nullptr, nullptr,
                                                                 qkvb, QKVDIM, CDIM);
    attn_tc<<<dim3(25, BATCH * NHEAD), 128>>>(qkvb, ob);
    gemm_tc<1><<<dim3(CDIM / 128, TTOK / 128), 128, GSMEM_B>>>(ob, proj_w, proj_b, t,
                                                               t, CDIM, CDIM);
    ln_kernel<<<TTOK, 256>>>(t, ln2_w, ln2_b, hbuf);
    gemm_tc<2><<<dim3(HID / 128, TTOK / 128), 128, GSMEM_B>>>(hbuf, fc1_w, fc1_b, nullptr,
                                                              mlpb, HID, CDIM);
    gemm_tc<1><<<dim3(CDIM / 128, TTOK / 128), 128, GSMEM_B>>>(mlpb, fc2_w, fc2_b, t,
                                                               t, CDIM, HID);
    untok_kernel<<<dim3(TOK / 32, CDIM / 32, BATCH), dim3(32, 8)>>>(out);
}

// round 9
// speedup vs baseline: 1.6374x; 1.6374x over previous
#include <cuda_runtime.h>
#include <cuda_fp16.h>
#include <math.h>
#include <stdint.h>

#define TOK    1568
#define BATCH  4
#define CDIM   768
#define TTOK   (BATCH*TOK)
#define QKVDIM 2304
#define HID    3072
#define NHEAD  12
#define DHEAD  64

#define W_QKV  0
#define W_PROJ 1769472
#define W_FC1  2359296
#define W_FC2  4718592
#define W_TOT  7077888

__device__ float  g_t[TTOK * CDIM];
__device__ float  g_qkv[TTOK * QKVDIM];
__device__ float  g_o[TTOK * CDIM];
__device__ __half g_h16[TTOK * CDIM];
__device__ __half g_o16[TTOK * CDIM];
__device__ __half g_m16[TTOK * HID];
__device__ __half g_w16[W_TOT];

// ---------------- ptx helpers ----------------
__device__ __forceinline__ void mma_tf32(float* d, const uint32_t* a, const uint32_t* b) {
    asm volatile(
        "mma.sync.aligned.m16n8k8.row.col.f32.tf32.tf32.f32 "
        "{%0,%1,%2,%3}, {%4,%5,%6,%7}, {%8,%9}, {%0,%1,%2,%3};"
        : "+f"(d[0]), "+f"(d[1]), "+f"(d[2]), "+f"(d[3])
        : "r"(a[0]), "r"(a[1]), "r"(a[2]), "r"(a[3]), "r"(b[0]), "r"(b[1]));
}
__device__ __forceinline__ void mma_f16(float* d, const uint32_t* a, const uint32_t* b) {
    asm volatile(
        "mma.sync.aligned.m16n8k16.row.col.f32.f16.f16.f32 "
        "{%0,%1,%2,%3}, {%4,%5,%6,%7}, {%8,%9}, {%0,%1,%2,%3};"
        : "+f"(d[0]), "+f"(d[1]), "+f"(d[2]), "+f"(d[3])
        : "r"(a[0]), "r"(a[1]), "r"(a[2]), "r"(a[3]), "r"(b[0]), "r"(b[1]));
}
__device__ __forceinline__ void cp16(uint32_t dst, const void* src) {
    asm volatile("cp.async.cg.shared.global [%0], [%1], 16;" :: "r"(dst), "l"(src));
}
__device__ __forceinline__ void cp_commit() { asm volatile("cp.async.commit_group;"); }
template <int N> __device__ __forceinline__ void cp_wait() {
    asm volatile("cp.async.wait_group %0;" :: "n"(N));
}
__device__ __forceinline__ float gelu_exact(float v) {
    return 0.5f * v * (1.f + erff(v * 0.70710678118654752f));
}

// ---------------- fp32 -> fp16 convert ----------------
__global__ void cvt16(const float* __restrict__ src, __half* __restrict__ dst, int n) {
    int i = blockIdx.x * 256 + threadIdx.x;
    if (i < n) dst[i] = __float2half(src[i]);
}

// ---------------- conv + bias + residual + tokenize ----------------
__global__ void conv_pos_kernel(const float* __restrict__ x,
                                const float* __restrict__ pw,
                                const float* __restrict__ pb) {
    int bc = blockIdx.x;
    int c  = bc % CDIM;
    int b  = bc / CDIM;
    __shared__ float sx[TOK];
    __shared__ float sw[27];
    int tid = threadIdx.x;
    const float* xs = x + (size_t)bc * TOK;
    for (int i = tid; i < TOK; i += 256) sx[i] = xs[i];
    if (tid < 27) sw[tid] = pw[c * 27 + tid];
    __syncthreads();
    float pbv = pb[c];
    for (int idx = tid; idx < TOK; idx += 256) {
        int d = idx / 196; int r = idx - d * 196;
        int h = r / 14;    int w = r - h * 14;
        float acc = 0.f;
        #pragma unroll
        for (int kd = 0; kd < 3; kd++) {
            int dd = d + kd - 1;
            if (dd < 0 || dd >= 8) continue;
            #pragma unroll
            for (int kh = 0; kh < 3; kh++) {
                int hh = h + kh - 1;
                if (hh < 0 || hh >= 14) continue;
                #pragma unroll
                for (int kw = 0; kw < 3; kw++) {
                    int ww = w + kw - 1;
                    if (ww < 0 || ww >= 14) continue;
                    acc += sw[kd * 9 + kh * 3 + kw] * sx[dd * 196 + hh * 14 + ww];
                }
            }
        }
        g_t[(size_t)(b * TOK + idx) * CDIM + c] = sx[idx] + acc + pbv;
    }
}

// ---------------- LayerNorm -> fp16 ----------------
__global__ void ln_kernel(const float* __restrict__ in, const float* __restrict__ w,
                          const float* __restrict__ bsrc, __half* __restrict__ out) {
    int t = blockIdx.x;
    int tid = threadIdx.x;
    const float* row = in + (size_t)t * CDIM;
    float v0 = row[tid], v1 = row[tid + 256], v2 = row[tid + 512];
    float s  = v0 + v1 + v2;
    float sq = v0 * v0 + v1 * v1 + v2 * v2;
    #pragma unroll
    for (int off = 16; off; off >>= 1) {
        s  += __shfl_xor_sync(0xffffffffu, s,  off);
        sq += __shfl_xor_sync(0xffffffffu, sq, off);
    }
    __shared__ float ss[8], ssq[8];
    int wid = tid >> 5, lid = tid & 31;
    if (lid == 0) { ss[wid] = s; ssq[wid] = sq; }
    __syncthreads();
    if (tid < 32) {
        s  = (lid < 8) ? ss[lid]  : 0.f;
        sq = (lid < 8) ? ssq[lid] : 0.f;
        #pragma unroll
        for (int off = 4; off; off >>= 1) {
            s  += __shfl_xor_sync(0xffffffffu, s,  off);
            sq += __shfl_xor_sync(0xffffffffu, sq, off);
        }
        if (lid == 0) { ss[0] = s; ssq[0] = sq; }
    }
    __syncthreads();
    float mean = ss[0] * (1.f / CDIM);
    float var  = ssq[0] * (1.f / CDIM) - mean * mean;
    float rs   = rsqrtf(var + 1e-5f);
    __half* orow = out + (size_t)t * CDIM;
    orow[tid]       = __float2half((v0 - mean) * rs * w[tid]       + bsrc[tid]);
    orow[tid + 256] = __float2half((v1 - mean) * rs * w[tid + 256] + bsrc[tid + 256]);
    orow[tid + 512] = __float2half((v2 - mean) * rs * w[tid + 512] + bsrc[tid + 512]);
}

// ---------------- fp16 mma GEMM: BK=32 halves, 3-stage cp.async, 1 barrier/chunk ----------------
// C[M,N] = A[M,K] @ B[N,K]^T (fp16 in, fp32 acc). Block 128x128, 256 thr, warp tile 64x32.
// Smem rows: 16 data words (32 halves) + 4 pad = 20 words; conflict-free pattern as R7.
// MODE 0: Cf = acc ; MODE 1: Cf = acc + bias + resid ; MODE 2: Ch = gelu(acc + bias)
#define GH_STRIDE 20
#define GH_MATW   (128 * GH_STRIDE)
#define GH_STAGEW (2 * GH_MATW)
#define GHSMEM_B  (3 * GH_STAGEW * 4)   // 61440 bytes

template <int MODE>
__global__ void __launch_bounds__(256, 2)
gemm_h(const __half* __restrict__ A, const __half* __restrict__ B,
       const float* __restrict__ bias, const float* __restrict__ resid,
       float* __restrict__ Cf, __half* __restrict__ Ch, int N, int K) {
    extern __shared__ __align__(16) uint32_t smw[];
    int tid = threadIdx.x;
    int lane = tid & 31, warp = tid >> 5;
    int wm = warp >> 2, wn = warp & 3;
    int m0 = blockIdx.y << 7, n0 = blockIdx.x << 7;

    // loader: thread -> row tid>>1, part tid&1 (two cp16 per matrix)
    int lrow = tid >> 1;
    int lpart = tid & 1;
    const __half* Ag = A + (size_t)(m0 + lrow) * K + lpart * 16;
    const __half* Bg = B + (size_t)(n0 + lrow) * K + lpart * 16;
    uint32_t sa0 = (uint32_t)__cvta_generic_to_shared(smw) + (lrow * GH_STRIDE + lpart * 8) * 4;
    uint32_t sb0 = sa0 + GH_MATW * 4;

    int nch = K >> 5;
    auto load_chunk = [&](int ch) {
        uint32_t d = (uint32_t)(ch % 3) * (GH_STAGEW * 4);
        int off = ch << 5;
        cp16(sa0 + d, Ag + off); cp16(sa0 + d + 16, Ag + off + 8);
        cp16(sb0 + d, Bg + off); cp16(sb0 + d + 16, Bg + off + 8);
        cp_commit();
    };

    float acc[4][4][4];
    #pragma unroll
    for (int mi = 0; mi < 4; mi++)
        #pragma unroll
        for (int ni = 0; ni < 4; ni++)
            #pragma unroll
            for (int r = 0; r < 4; r++) acc[mi][ni][r] = 0.f;

    int mbase = wm * 64 + (lane >> 2);
    int nbase = wn * 32 + (lane >> 2);
    int kq = lane & 3;

    load_chunk(0);
    load_chunk(1);
    for (int ch = 0; ch < nch; ch++) {
        if (ch < nch - 1) cp_wait<1>(); else cp_wait<0>();
        __syncthreads();
        if (ch + 2 < nch) load_chunk(ch + 2);
        const uint32_t* as = smw + (ch % 3) * GH_STAGEW;
        const uint32_t* bs = as + GH_MATW;
        #pragma unroll
        for (int kt = 0; kt < 2; kt++) {
            int kw = kq + kt * 8;
            uint32_t af[4][4], bf[4][2];
            #pragma unroll
            for (int mi = 0; mi < 4; mi++) {
                int m = mbase + mi * 16;
                af[mi][0] = as[m * GH_STRIDE + kw];
                af[mi][1] = as[(m + 8) * GH_STRIDE + kw];
                af[mi][2] = as[m * GH_STRIDE + kw + 4];
                af[mi][3] = as[(m + 8) * GH_STRIDE + kw + 4];
            }
            #pragma unroll
            for (int ni = 0; ni < 4; ni++) {
                int n = nbase + ni * 8;
                bf[ni][0] = bs[n * GH_STRIDE + kw];
                bf[ni][1] = bs[n * GH_STRIDE + kw + 4];
            }
            #pragma unroll
            for (int mi = 0; mi < 4; mi++)
                #pragma unroll
                for (int ni = 0; ni < 4; ni++)
                    mma_f16(acc[mi][ni], af[mi], bf[ni]);
        }
    }

    // epilogue (D layout: c0,c1 at (r0, 2q), c2,c3 at (r0+8, 2q))
    int r0 = lane >> 2, cq = (lane & 3) * 2;
    #pragma unroll
    for (int mi = 0; mi < 4; mi++) {
        int rowA = m0 + wm * 64 + mi * 16 + r0;
        int rowB = rowA + 8;
        #pragma unroll
        for (int ni = 0; ni < 4; ni++) {
            int col = n0 + wn * 32 + ni * 8 + cq;
            float2 va = make_float2(acc[mi][ni][0], acc[mi][ni][1]);
            float2 vb = make_float2(acc[mi][ni][2], acc[mi][ni][3]);
            if (MODE == 0) {
                *(float2*)(Cf + (size_t)rowA * N + col) = va;
                *(float2*)(Cf + (size_t)rowB * N + col) = vb;
            } else if (MODE == 1) {
                float2 bv = *(const float2*)(bias + col);
                float2 ra = *(const float2*)(resid + (size_t)rowA * N + col);
                float2 rb = *(const float2*)(resid + (size_t)rowB * N + col);
                va.x += bv.x + ra.x; va.y += bv.y + ra.y;
                vb.x += bv.x + rb.x; vb.y += bv.y + rb.y;
                *(float2*)(Cf + (size_t)rowA * N + col) = va;
                *(float2*)(Cf + (size_t)rowB * N + col) = vb;
            } else {
                float2 bv = *(const float2*)(bias + col);
                va.x = gelu_exact(va.x + bv.x); va.y = gelu_exact(va.y + bv.y);
                vb.x = gelu_exact(vb.x + bv.x); vb.y = gelu_exact(vb.y + bv.y);
                *(__half2*)(Ch + (size_t)rowA * N + col) = __floats2half2_rn(va.x, va.y);
                *(__half2*)(Ch + (size_t)rowB * N + col) = __floats2half2_rn(vb.x, vb.y);
            }
        }
    }
}

// ---------------- tf32 flash attention (proven R7 version, unchanged) ----------------
__global__ void __launch_bounds__(128)
attn_tc(const float* __restrict__ qkv, float* __restrict__ o) {
    __shared__ __align__(16) float KP[64 * 68];
    __shared__ __align__(16) float Vs[64 * 72];
    int tid = threadIdx.x, lane = tid & 31, warp = tid >> 5;
    int bh = blockIdx.y;
    int b = bh / NHEAD, h = bh % NHEAD;
    int q0 = blockIdx.x * 64;
    const float* base = qkv + (size_t)b * TOK * QKVDIM + h * DHEAD;

    int r0 = lane >> 2, kq = lane & 3;
    uint32_t qf[8][4];
    {
        int qa = q0 + warp * 16 + r0;
        int qb = qa + 8;
        const float* pa = base + (size_t)qa * QKVDIM;
        const float* pb = base + (size_t)qb * QKVDIM;
        bool va = qa < TOK, vb = qb < TOK;
        #pragma unroll
        for (int kt = 0; kt < 8; kt++) {
            int k = kt * 8 + kq;
            qf[kt][0] = va ? __float_as_uint(pa[k] * 0.125f) : 0u;
            qf[kt][1] = vb ? __float_as_uint(pb[k] * 0.125f) : 0u;
            qf[kt][2] = va ? __float_as_uint(pa[k + 4] * 0.125f) : 0u;
            qf[kt][3] = vb ? __float_as_uint(pb[k + 4] * 0.125f) : 0u;
        }
    }

    float oacc[8][4];
    #pragma unroll
    for (int nt = 0; nt < 8; nt++)
        #pragma unroll
        for (int rr = 0; rr < 4; rr++) oacc[nt][rr] = 0.f;
    float mi0 = -1e30f, mi1 = -1e30f, li0 = 0.f, li1 = 0.f;

    for (int kc = 0; kc < 25; kc++) {
        __syncthreads();
        #pragma unroll
        for (int i = 0; i < 8; i++) {
            int q = tid + i * 128;
            int key = q >> 4;
            int d4  = (q & 15) << 2;
            int kg = kc * 64 + key;
            float4 kv = make_float4(0.f, 0.f, 0.f, 0.f);
            float4 vv = make_float4(0.f, 0.f, 0.f, 0.f);
            if (kg < TOK) {
                kv = *(const float4*)(base + (size_t)kg * QKVDIM + CDIM + d4);
                vv = *(const float4*)(base + (size_t)kg * QKVDIM + 2 * CDIM + d4);
            }
            *(float4*)&KP[key * 68 + d4] = kv;
            *(float4*)&Vs[key * 72 + d4] = vv;
        }
        __syncthreads();

        float s[8][4];
        #pragma unroll
        for (int ni = 0; ni < 8; ni++)
            #pragma unroll
            for (int rr = 0; rr < 4; rr++) s[ni][rr] = 0.f;
        #pragma unroll
        for (int kt = 0; kt < 8; kt++) {
            int kk = kt * 8 + kq;
            #pragma unroll
            for (int ni = 0; ni < 8; ni++) {
                int n = ni * 8 + r0;
                uint32_t bf[2];
                bf[0] = __float_as_uint(KP[n * 68 + kk]);
                bf[1] = __float_as_uint(KP[n * 68 + kk + 4]);
                mma_tf32(s[ni], qf[kt], bf);
            }
        }
        if (kc == 24) {
            #pragma unroll
            for (int ni = 0; ni < 8; ni++) {
                int c = kc * 64 + ni * 8 + kq * 2;
                if (c >= TOK)     { s[ni][0] = -1e30f; s[ni][2] = -1e30f; }
                if (c + 1 >= TOK) { s[ni][1] = -1e30f; s[ni][3] = -1e30f; }
            }
        }
        float mr0 = -1e30f, mr1 = -1e30f;
        #pragma unroll
        for (int ni = 0; ni < 8; ni++) {
            mr0 = fmaxf(mr0, fmaxf(s[ni][0], s[ni][1]));
            mr1 = fmaxf(mr1, fmaxf(s[ni][2], s[ni][3]));
        }
        mr0 = fmaxf(mr0, __shfl_xor_sync(0xffffffffu, mr0, 1));
        mr0 = fmaxf(mr0, __shfl_xor_sync(0xffffffffu, mr0, 2));
        mr1 = fmaxf(mr1, __shfl_xor_sync(0xffffffffu, mr1, 1));
        mr1 = fmaxf(mr1, __shfl_xor_sync(0xffffffffu, mr1, 2));
        float mn0 = fmaxf(mi0, mr0), mn1 = fmaxf(mi1, mr1);
        float a0 = __expf(mi0 - mn0), a1 = __expf(mi1 - mn1);
        float sum0 = 0.f, sum1 = 0.f;
        #pragma unroll
        for (int ni = 0; ni < 8; ni++) {
            s[ni][0] = __expf(s[ni][0] - mn0);
            s[ni][1] = __expf(s[ni][1] - mn0);
            s[ni][2] = __expf(s[ni][2] - mn1);
            s[ni][3] = __expf(s[ni][3] - mn1);
            sum0 += s[ni][0] + s[ni][1];
            sum1 += s[ni][2] + s[ni][3];
        }
        sum0 += __shfl_xor_sync(0xffffffffu, sum0, 1);
        sum0 += __shfl_xor_sync(0xffffffffu, sum0, 2);
        sum1 += __shfl_xor_sync(0xffffffffu, sum1, 1);
        sum1 += __shfl_xor_sync(0xffffffffu, sum1, 2);
        li0 = li0 * a0 + sum0; li1 = li1 * a1 + sum1;
        mi0 = mn0; mi1 = mn1;
        #pragma unroll
        for (int nt = 0; nt < 8; nt++) {
            oacc[nt][0] *= a0; oacc[nt][1] *= a0;
            oacc[nt][2] *= a1; oacc[nt][3] *= a1;
        }
        __syncthreads();
        {
            int prow = warp * 16 + r0;
            #pragma unroll
            for (int ni = 0; ni < 8; ni++) {
                int col = ni * 8 + kq * 2;
                *(float2*)&KP[prow * 68 + col]       = make_float2(s[ni][0], s[ni][1]);
                *(float2*)&KP[(prow + 8) * 68 + col] = make_float2(s[ni][2], s[ni][3]);
            }
        }
        __syncwarp();
        #pragma unroll
        for (int kt = 0; kt < 8; kt++) {
            int kk = kt * 8 + kq;
            uint32_t pf[4];
            int prow = warp * 16 + r0;
            pf[0] = __float_as_uint(KP[prow * 68 + kk]);
            pf[1] = __float_as_uint(KP[(prow + 8) * 68 + kk]);
            pf[2] = __float_as_uint(KP[prow * 68 + kk + 4]);
            pf[3] = __float_as_uint(KP[(prow + 8) * 68 + kk + 4]);
            #pragma unroll
            for (int nt = 0; nt < 8; nt++) {
                int n = nt * 8 + r0;
                uint32_t bf[2];
                bf[0] = __float_as_uint(Vs[kk * 72 + n]);
                bf[1] = __float_as_uint(Vs[(kk + 4) * 72 + n]);
                mma_tf32(oacc[nt], pf, bf);
            }
        }
    }

    int qa = q0 + warp * 16 + r0;
    int qb = qa + 8;
    float inv0 = 1.f / li0, inv1 = 1.f / li1;
    #pragma unroll
    for (int nt = 0; nt < 8; nt++) {
        int col = h * DHEAD + nt * 8 + kq * 2;
        if (qa < TOK)
            *(float2*)(o + (size_t)(b * TOK + qa) * CDIM + col) =
                make_float2(oacc[nt][0] * inv0, oacc[nt][1] * inv0);
        if (qb < TOK)
            *(float2*)(o + (size_t)(b * TOK + qb) * CDIM + col) =
                make_float2(oacc[nt][2] * inv1, oacc[nt][3] * inv1);
    }
}

// ---------------- untokenize ----------------
__global__ void untok_kernel(float* __restrict__ out) {
    __shared__ float tile[32][33];
    int b  = blockIdx.z;
    int s0 = blockIdx.x * 32;
    int c0 = blockIdx.y * 32;
    int tx = threadIdx.x, ty = threadIdx.y;
    #pragma unroll
    for (int r = ty; r < 32; r += 8)
        tile[r][tx] = g_t[(size_t)(b * TOK + s0 + r) * CDIM + c0 + tx];
    __syncthreads();
    #pragma unroll
    for (int r = ty; r < 32; r += 8)
        out[(size_t)(b * CDIM + c0 + r) * TOK + s0 + tx] = tile[tx][r];
}

// ---------------- launch ----------------
extern "C" void kernel_launch(void* const* d_in, const int* in_sizes, int n_in,
                              void* d_out, int out_size) {
    const float* x      = (const float*)d_in[0];
    const float* pos_w  = (const float*)d_in[1];
    const float* pos_b  = (const float*)d_in[2];
    const float* ln1_w  = (const float*)d_in[3];
    const float* ln1_b  = (const float*)d_in[4];
    const float* qkv_w  = (const float*)d_in[5];
    const float* proj_w = (const float*)d_in[6];
    const float* proj_b = (const float*)d_in[7];
    const float* ln2_w  = (const float*)d_in[8];
    const float* ln2_b  = (const float*)d_in[9];
    const float* fc1_w  = (const float*)d_in[10];
    const float* fc1_b  = (const float*)d_in[11];
    const float* fc2_w  = (const float*)d_in[12];
    const float* fc2_b  = (const float*)d_in[13];
    float* out = (float*)d_out;

    float *t, *qkvb, *ob;
    __half *h16, *o16, *m16, *w16;
    cudaGetSymbolAddress((void**)&t,    g_t);
    cudaGetSymbolAddress((void**)&qkvb, g_qkv);
    cudaGetSymbolAddress((void**)&ob,   g_o);
    cudaGetSymbolAddress((void**)&h16,  g_h16);
    cudaGetSymbolAddress((void**)&o16,  g_o16);
    cudaGetSymbolAddress((void**)&m16,  g_m16);
    cudaGetSymbolAddress((void**)&w16,  g_w16);

    cudaFuncSetAttribute(gemm_h<0>, cudaFuncAttributeMaxDynamicSharedMemorySize, GHSMEM_B);
    cudaFuncSetAttribute(gemm_h<1>, cudaFuncAttributeMaxDynamicSharedMemorySize, GHSMEM_B);
    cudaFuncSetAttribute(gemm_h<2>, cudaFuncAttributeMaxDynamicSharedMemorySize, GHSMEM_B);

    // weight conversions (deterministic, every launch)
    cvt16<<<(QKVDIM * CDIM + 255) / 256, 256>>>(qkv_w,  w16 + W_QKV,  QKVDIM * CDIM);
    cvt16<<<(CDIM * CDIM + 255) / 256, 256>>>(proj_w,  w16 + W_PROJ, CDIM * CDIM);
    cvt16<<<(HID * CDIM + 255) / 256, 256>>>(fc1_w,    w16 + W_FC1,  HID * CDIM);
    cvt16<<<(CDIM * HID + 255) / 256, 256>>>(fc2_w,    w16 + W_FC2,  CDIM * HID);

    conv_pos_kernel<<<BATCH * CDIM, 256>>>(x, pos_w, pos_b);
    ln_kernel<<<TTOK, 256>>>(t, ln1_w, ln1_b, h16);
    gemm_h<0><<<dim3(QKVDIM / 128, TTOK / 128), 256, GHSMEM_B>>>(
        h16, w16 + W_QKV, nullptr, nullptr, qkvb, nullptr, QKVDIM, CDIM);
    attn_tc<<<dim3(25, BATCH * NHEAD), 128>>>(qkvb, ob);
    cvt16<<<(TTOK * CDIM + 255) / 256, 256>>>(ob, o16, TTOK * CDIM);
    gemm_h<1><<<dim3(CDIM / 128, TTOK / 128), 256, GHSMEM_B>>>(
        o16, w16 + W_PROJ, proj_b, t, t, nullptr, CDIM, CDIM);
    ln_kernel<<<TTOK, 256>>>(t, ln2_w, ln2_b, h16);
    gemm_h<2><<<dim3(HID / 128, TTOK / 128), 256, GHSMEM_B>>>(
        h16, w16 + W_FC1, fc1_b, nullptr, nullptr, m16, HID, CDIM);
    gemm_h<1><<<dim3(CDIM / 128, TTOK / 128), 256, GHSMEM_B>>>(
        m16, w16 + W_FC2, fc2_b, t, t, nullptr, CDIM, HID);
    untok_kernel<<<dim3(TOK / 32, CDIM / 32, BATCH), dim3(32, 8)>>>(out);
}

// round 10
// speedup vs baseline: 1.8422x; 1.1251x over previous
#include <cuda_runtime.h>
#include <cuda_fp16.h>
#include <math.h>
#include <stdint.h>

#define TOK    1568
#define BATCH  4
#define CDIM   768
#define TTOK   (BATCH*TOK)
#define QKVDIM 2304
#define HID    3072
#define NHEAD  12
#define DHEAD  64

#define W_QKV  0
#define W_PROJ 1769472
#define W_FC1  2359296
#define W_FC2  4718592
#define W_TOT  7077888

__device__ float  g_t[TTOK * CDIM];
__device__ __half g_q16[TTOK * QKVDIM];
__device__ __half g_h16[TTOK * CDIM];
__device__ __half g_o16[TTOK * CDIM];
__device__ __half g_m16[TTOK * HID];
__device__ __half g_w16[W_TOT];

// ---------------- ptx helpers ----------------
__device__ __forceinline__ void mma_f16(float* d, const uint32_t* a, const uint32_t* b) {
    asm volatile(
        "mma.sync.aligned.m16n8k16.row.col.f32.f16.f16.f32 "
        "{%0,%1,%2,%3}, {%4,%5,%6,%7}, {%8,%9}, {%0,%1,%2,%3};"
        : "+f"(d[0]), "+f"(d[1]), "+f"(d[2]), "+f"(d[3])
        : "r"(a[0]), "r"(a[1]), "r"(a[2]), "r"(a[3]), "r"(b[0]), "r"(b[1]));
}
__device__ __forceinline__ void cp16(uint32_t dst, const void* src) {
    asm volatile("cp.async.cg.shared.global [%0], [%1], 16;" :: "r"(dst), "l"(src));
}
__device__ __forceinline__ void cp_commit() { asm volatile("cp.async.commit_group;"); }
template <int N> __device__ __forceinline__ void cp_wait() {
    asm volatile("cp.async.wait_group %0;" :: "n"(N));
}
__device__ __forceinline__ float gelu_exact(float v) {
    return 0.5f * v * (1.f + erff(v * 0.70710678118654752f));
}

// ---------------- fp32 -> fp16 convert ----------------
__global__ void cvt16(const float* __restrict__ src, __half* __restrict__ dst, int n) {
    int i = blockIdx.x * 256 + threadIdx.x;
    if (i < n) dst[i] = __float2half(src[i]);
}

// ---------------- conv + bias + residual + tokenize ----------------
__global__ void conv_pos_kernel(const float* __restrict__ x,
                                const float* __restrict__ pw,
                                const float* __restrict__ pb) {
    int bc = blockIdx.x;
    int c  = bc % CDIM;
    int b  = bc / CDIM;
    __shared__ float sx[TOK];
    __shared__ float sw[27];
    int tid = threadIdx.x;
    const float* xs = x + (size_t)bc * TOK;
    for (int i = tid; i < TOK; i += 256) sx[i] = xs[i];
    if (tid < 27) sw[tid] = pw[c * 27 + tid];
    __syncthreads();
    float pbv = pb[c];
    for (int idx = tid; idx < TOK; idx += 256) {
        int d = idx / 196; int r = idx - d * 196;
        int h = r / 14;    int w = r - h * 14;
        float acc = 0.f;
        #pragma unroll
        for (int kd = 0; kd < 3; kd++) {
            int dd = d + kd - 1;
            if (dd < 0 || dd >= 8) continue;
            #pragma unroll
            for (int kh = 0; kh < 3; kh++) {
                int hh = h + kh - 1;
                if (hh < 0 || hh >= 14) continue;
                #pragma unroll
                for (int kw = 0; kw < 3; kw++) {
                    int ww = w + kw - 1;
                    if (ww < 0 || ww >= 14) continue;
                    acc += sw[kd * 9 + kh * 3 + kw] * sx[dd * 196 + hh * 14 + ww];
                }
            }
        }
        g_t[(size_t)(b * TOK + idx) * CDIM + c] = sx[idx] + acc + pbv;
    }
}

// ---------------- LayerNorm -> fp16 ----------------
__global__ void ln_kernel(const float* __restrict__ in, const float* __restrict__ w,
                          const float* __restrict__ bsrc, __half* __restrict__ out) {
    int t = blockIdx.x;
    int tid = threadIdx.x;
    const float* row = in + (size_t)t * CDIM;
    float v0 = row[tid], v1 = row[tid + 256], v2 = row[tid + 512];
    float s  = v0 + v1 + v2;
    float sq = v0 * v0 + v1 * v1 + v2 * v2;
    #pragma unroll
    for (int off = 16; off; off >>= 1) {
        s  += __shfl_xor_sync(0xffffffffu, s,  off);
        sq += __shfl_xor_sync(0xffffffffu, sq, off);
    }
    __shared__ float ss[8], ssq[8];
    int wid = tid >> 5, lid = tid & 31;
    if (lid == 0) { ss[wid] = s; ssq[wid] = sq; }
    __syncthreads();
    if (tid < 32) {
        s  = (lid < 8) ? ss[lid]  : 0.f;
        sq = (lid < 8) ? ssq[lid] : 0.f;
        #pragma unroll
        for (int off = 4; off; off >>= 1) {
            s  += __shfl_xor_sync(0xffffffffu, s,  off);
            sq += __shfl_xor_sync(0xffffffffu, sq, off);
        }
        if (lid == 0) { ss[0] = s; ssq[0] = sq; }
    }
    __syncthreads();
    float mean = ss[0] * (1.f / CDIM);
    float var  = ssq[0] * (1.f / CDIM) - mean * mean;
    float rs   = rsqrtf(var + 1e-5f);
    __half* orow = out + (size_t)t * CDIM;
    orow[tid]       = __float2half((v0 - mean) * rs * w[tid]       + bsrc[tid]);
    orow[tid + 256] = __float2half((v1 - mean) * rs * w[tid + 256] + bsrc[tid + 256]);
    orow[tid + 512] = __float2half((v2 - mean) * rs * w[tid + 512] + bsrc[tid + 512]);
}

// ---------------- fp16 mma GEMM (R9 winner + MODE 3) ----------------
// MODE 0: Cf=acc ; 1: Cf=acc+bias+resid ; 2: Ch=gelu(acc+bias) ; 3: Ch=acc
#define GH_STRIDE 20
#define GH_MATW   (128 * GH_STRIDE)
#define GH_STAGEW (2 * GH_MATW)
#define GHSMEM_B  (3 * GH_STAGEW * 4)

template <int MODE>
__global__ void __launch_bounds__(256, 2)
gemm_h(const __half* __restrict__ A, const __half* __restrict__ B,
       const float* __restrict__ bias, const float* __restrict__ resid,
       float* __restrict__ Cf, __half* __restrict__ Ch, int N, int K) {
    extern __shared__ __align__(16) uint32_t smw[];
    int tid = threadIdx.x;
    int lane = tid & 31, warp = tid >> 5;
    int wm = warp >> 2, wn = warp & 3;
    int m0 = blockIdx.y << 7, n0 = blockIdx.x << 7;

    int lrow = tid >> 1;
    int lpart = tid & 1;
    const __half* Ag = A + (size_t)(m0 + lrow) * K + lpart * 16;
    const __half* Bg = B + (size_t)(n0 + lrow) * K + lpart * 16;
    uint32_t sa0 = (uint32_t)__cvta_generic_to_shared(smw) + (lrow * GH_STRIDE + lpart * 8) * 4;
    uint32_t sb0 = sa0 + GH_MATW * 4;

    int nch = K >> 5;
    auto load_chunk = [&](int ch) {
        uint32_t d = (uint32_t)(ch % 3) * (GH_STAGEW * 4);
        int off = ch << 5;
        cp16(sa0 + d, Ag + off); cp16(sa0 + d + 16, Ag + off + 8);
        cp16(sb0 + d, Bg + off); cp16(sb0 + d + 16, Bg + off + 8);
        cp_commit();
    };

    float acc[4][4][4];
    #pragma unroll
    for (int mi = 0; mi < 4; mi++)
        #pragma unroll
        for (int ni = 0; ni < 4; ni++)
            #pragma unroll
            for (int r = 0; r < 4; r++) acc[mi][ni][r] = 0.f;

    int mbase = wm * 64 + (lane >> 2);
    int nbase = wn * 32 + (lane >> 2);
    int kq = lane & 3;

    load_chunk(0);
    load_chunk(1);
    for (int ch = 0; ch < nch; ch++) {
        if (ch < nch - 1) cp_wait<1>(); else cp_wait<0>();
        __syncthreads();
        if (ch + 2 < nch) load_chunk(ch + 2);
        const uint32_t* as = smw + (ch % 3) * GH_STAGEW;
        const uint32_t* bs = as + GH_MATW;
        #pragma unroll
        for (int kt = 0; kt < 2; kt++) {
            int kw = kq + kt * 8;
            uint32_t af[4][4], bf[4][2];
            #pragma unroll
            for (int mi = 0; mi < 4; mi++) {
                int m = mbase + mi * 16;
                af[mi][0] = as[m * GH_STRIDE + kw];
                af[mi][1] = as[(m + 8) * GH_STRIDE + kw];
                af[mi][2] = as[m * GH_STRIDE + kw + 4];
                af[mi][3] = as[(m + 8) * GH_STRIDE + kw + 4];
            }
            #pragma unroll
            for (int ni = 0; ni < 4; ni++) {
                int n = nbase + ni * 8;
                bf[ni][0] = bs[n * GH_STRIDE + kw];
                bf[ni][1] = bs[n * GH_STRIDE + kw + 4];
            }
            #pragma unroll
            for (int mi = 0; mi < 4; mi++)
                #pragma unroll
                for (int ni = 0; ni < 4; ni++)
                    mma_f16(acc[mi][ni], af[mi], bf[ni]);
        }
    }

    int r0 = lane >> 2, cq = (lane & 3) * 2;
    #pragma unroll
    for (int mi = 0; mi < 4; mi++) {
        int rowA = m0 + wm * 64 + mi * 16 + r0;
        int rowB = rowA + 8;
        #pragma unroll
        for (int ni = 0; ni < 4; ni++) {
            int col = n0 + wn * 32 + ni * 8 + cq;
            float2 va = make_float2(acc[mi][ni][0], acc[mi][ni][1]);
            float2 vb = make_float2(acc[mi][ni][2], acc[mi][ni][3]);
            if (MODE == 0) {
                *(float2*)(Cf + (size_t)rowA * N + col) = va;
                *(float2*)(Cf + (size_t)rowB * N + col) = vb;
            } else if (MODE == 1) {
                float2 bv = *(const float2*)(bias + col);
                float2 ra = *(const float2*)(resid + (size_t)rowA * N + col);
                float2 rb = *(const float2*)(resid + (size_t)rowB * N + col);
                va.x += bv.x + ra.x; va.y += bv.y + ra.y;
                vb.x += bv.x + rb.x; vb.y += bv.y + rb.y;
                *(float2*)(Cf + (size_t)rowA * N + col) = va;
                *(float2*)(Cf + (size_t)rowB * N + col) = vb;
            } else if (MODE == 2) {
                float2 bv = *(const float2*)(bias + col);
                va.x = gelu_exact(va.x + bv.x); va.y = gelu_exact(va.y + bv.y);
                vb.x = gelu_exact(vb.x + bv.x); vb.y = gelu_exact(vb.y + bv.y);
                *(__half2*)(Ch + (size_t)rowA * N + col) = __floats2half2_rn(va.x, va.y);
                *(__half2*)(Ch + (size_t)rowB * N + col) = __floats2half2_rn(vb.x, vb.y);
            } else {
                *(__half2*)(Ch + (size_t)rowA * N + col) = __floats2half2_rn(va.x, va.y);
                *(__half2*)(Ch + (size_t)rowB * N + col) = __floats2half2_rn(vb.x, vb.y);
            }
        }
    }
}

// ---------------- fp16 flash attention ----------------
// 128 thr (4 warps), 64-query blocks, m16n8k16. K/P row-major stride 72 halves
// (72 = 8 mod 64 -> conflict-free half2 fragments); V transposed Vt[d][key].
__global__ void __launch_bounds__(128)
attn_h(const __half* __restrict__ qkv, __half* __restrict__ o) {
    __shared__ __align__(16) __half Ks[64 * 72];
    __shared__ __align__(16) __half Vt[64 * 72];
    __shared__ __align__(16) __half Ps[64 * 72];
    int tid = threadIdx.x, lane = tid & 31, warp = tid >> 5;
    int bh = blockIdx.y;
    int b = bh / NHEAD, h = bh % NHEAD;
    int q0 = blockIdx.x * 64;
    const __half* base = qkv + (size_t)b * TOK * QKVDIM + h * DHEAD;

    int r0 = lane >> 2, kq = lane & 3;
    int qa = q0 + warp * 16 + r0;
    int qb = qa + 8;
    bool va = qa < TOK, vb = qb < TOK;

    // Q fragments (scale 0.125 exact in fp16)
    uint32_t qf[4][4];
    {
        const __half2 sc = __floats2half2_rn(0.125f, 0.125f);
        const __half* pa = base + (size_t)qa * QKVDIM;
        const __half* pb = base + (size_t)qb * QKVDIM;
        #pragma unroll
        for (int kt = 0; kt < 4; kt++) {
            int k = kt * 16 + 2 * kq;
            __half2 v;
            v = va ? __hmul2(*(const __half2*)(pa + k), sc) : __floats2half2_rn(0.f, 0.f);
            qf[kt][0] = *(uint32_t*)&v;
            v = vb ? __hmul2(*(const __half2*)(pb + k), sc) : __floats2half2_rn(0.f, 0.f);
            qf[kt][1] = *(uint32_t*)&v;
            v = va ? __hmul2(*(const __half2*)(pa + k + 8), sc) : __floats2half2_rn(0.f, 0.f);
            qf[kt][2] = *(uint32_t*)&v;
            v = vb ? __hmul2(*(const __half2*)(pb + k + 8), sc) : __floats2half2_rn(0.f, 0.f);
            qf[kt][3] = *(uint32_t*)&v;
        }
    }

    float oacc[8][4];
    #pragma unroll
    for (int nt = 0; nt < 8; nt++)
        #pragma unroll
        for (int rr = 0; rr < 4; rr++) oacc[nt][rr] = 0.f;
    float mi0 = -1e30f, mi1 = -1e30f, li0 = 0.f, li1 = 0.f;
    int prow = warp * 16 + r0;

    for (int kc = 0; kc < 25; kc++) {
        __syncthreads();
        // K loader: 512 granules of 8 halves
        #pragma unroll
        for (int i = 0; i < 4; i++) {
            int g = tid + i * 128;
            int row = g >> 3, c8 = (g & 7) << 3;
            int kg = kc * 64 + row;
            uint4 v = make_uint4(0u, 0u, 0u, 0u);
            if (kg < TOK) v = *(const uint4*)(base + (size_t)kg * QKVDIM + CDIM + c8);
            *(uint4*)&Ks[row * 72 + c8] = v;
        }
        // V transpose loader: key-pairs x dim-groups
        #pragma unroll
        for (int i = 0; i < 2; i++) {
            int g = tid + i * 128;
            int kp = g >> 3, dg = (g & 7) << 3;
            int k0 = kc * 64 + 2 * kp;
            uint4 a = make_uint4(0u, 0u, 0u, 0u), bq = make_uint4(0u, 0u, 0u, 0u);
            if (k0 < TOK)     a  = *(const uint4*)(base + (size_t)k0 * QKVDIM + 2 * CDIM + dg);
            if (k0 + 1 < TOK) bq = *(const uint4*)(base + (size_t)(k0 + 1) * QKVDIM + 2 * CDIM + dg);
            const __half* ah = (const __half*)&a;
            const __half* bh2 = (const __half*)&bq;
            #pragma unroll
            for (int j = 0; j < 8; j++) {
                __half2 p; p.x = ah[j]; p.y = bh2[j];
                *(__half2*)&Vt[(dg + j) * 72 + 2 * kp] = p;
            }
        }
        __syncthreads();

        // S = Q K^T
        float s[8][4];
        #pragma unroll
        for (int ni = 0; ni < 8; ni++)
            #pragma unroll
            for (int rr = 0; rr < 4; rr++) s[ni][rr] = 0.f;
        #pragma unroll
        for (int kt = 0; kt < 4; kt++) {
            int kbase = kt * 16 + 2 * kq;
            #pragma unroll
            for (int ni = 0; ni < 8; ni++) {
                int n = ni * 8 + r0;
                uint32_t bf[2];
                bf[0] = *(const uint32_t*)&Ks[n * 72 + kbase];
                bf[1] = *(const uint32_t*)&Ks[n * 72 + kbase + 8];
                mma_f16(s[ni], qf[kt], bf);
            }
        }
        if (kc == 24) {
            #pragma unroll
            for (int ni = 0; ni < 8; ni++) {
                int c = kc * 64 + ni * 8 + kq * 2;
                if (c >= TOK)     { s[ni][0] = -1e30f; s[ni][2] = -1e30f; }
                if (c + 1 >= TOK) { s[ni][1] = -1e30f; s[ni][3] = -1e30f; }
            }
        }
        // online softmax
        float mr0 = -1e30f, mr1 = -1e30f;
        #pragma unroll
        for (int ni = 0; ni < 8; ni++) {
            mr0 = fmaxf(mr0, fmaxf(s[ni][0], s[ni][1]));
            mr1 = fmaxf(mr1, fmaxf(s[ni][2], s[ni][3]));
        }
        mr0 = fmaxf(mr0, __shfl_xor_sync(0xffffffffu, mr0, 1));
        mr0 = fmaxf(mr0, __shfl_xor_sync(0xffffffffu, mr0, 2));
        mr1 = fmaxf(mr1, __shfl_xor_sync(0xffffffffu, mr1, 1));
        mr1 = fmaxf(mr1, __shfl_xor_sync(0xffffffffu, mr1, 2));
        float mn0 = fmaxf(mi0, mr0), mn1 = fmaxf(mi1, mr1);
        float a0 = __expf(mi0 - mn0), a1 = __expf(mi1 - mn1);
        float sum0 = 0.f, sum1 = 0.f;
        #pragma unroll
        for (int ni = 0; ni < 8; ni++) {
            s[ni][0] = __expf(s[ni][0] - mn0);
            s[ni][1] = __expf(s[ni][1] - mn0);
            s[ni][2] = __expf(s[ni][2] - mn1);
            s[ni][3] = __expf(s[ni][3] - mn1);
            sum0 += s[ni][0] + s[ni][1];
            sum1 += s[ni][2] + s[ni][3];
        }
        sum0 += __shfl_xor_sync(0xffffffffu, sum0, 1);
        sum0 += __shfl_xor_sync(0xffffffffu, sum0, 2);
        sum1 += __shfl_xor_sync(0xffffffffu, sum1, 1);
        sum1 += __shfl_xor_sync(0xffffffffu, sum1, 2);
        li0 = li0 * a0 + sum0; li1 = li1 * a1 + sum1;
        mi0 = mn0; mi1 = mn1;
        #pragma unroll
        for (int nt = 0; nt < 8; nt++) {
            oacc[nt][0] *= a0; oacc[nt][1] *= a0;
            oacc[nt][2] *= a1; oacc[nt][3] *= a1;
        }
        // P write (warp-private rows; no block barrier needed)
        #pragma unroll
        for (int ni = 0; ni < 8; ni++) {
            int col = ni * 8 + kq * 2;
            *(__half2*)&Ps[prow * 72 + col]       = __floats2half2_rn(s[ni][0], s[ni][1]);
            *(__half2*)&Ps[(prow + 8) * 72 + col] = __floats2half2_rn(s[ni][2], s[ni][3]);
        }
        __syncwarp();
        // O += P V
        #pragma unroll
        for (int kt = 0; kt < 4; kt++) {
            int kbase = kt * 16 + 2 * kq;
            uint32_t pf[4];
            pf[0] = *(const uint32_t*)&Ps[prow * 72 + kbase];
            pf[1] = *(const uint32_t*)&Ps[(prow + 8) * 72 + kbase];
            pf[2] = *(const uint32_t*)&Ps[prow * 72 + kbase + 8];
            pf[3] = *(const uint32_t*)&Ps[(prow + 8) * 72 + kbase + 8];
            #pragma unroll
            for (int nt = 0; nt < 8; nt++) {
                int d = nt * 8 + r0;
                uint32_t bf[2];
                bf[0] = *(const uint32_t*)&Vt[d * 72 + kbase];
                bf[1] = *(const uint32_t*)&Vt[d * 72 + kbase + 8];
                mma_f16(oacc[nt], pf, bf);
            }
        }
    }

    float inv0 = 1.f / li0, inv1 = 1.f / li1;
    #pragma unroll
    for (int nt = 0; nt < 8; nt++) {
        int col = h * DHEAD + nt * 8 + kq * 2;
        if (va)
            *(__half2*)(o + (size_t)(b * TOK + qa) * CDIM + col) =
                __floats2half2_rn(oacc[nt][0] * inv0, oacc[nt][1] * inv0);
        if (vb)
            *(__half2*)(o + (size_t)(b * TOK + qb) * CDIM + col) =
                __floats2half2_rn(oacc[nt][2] * inv1, oacc[nt][3] * inv1);
    }
}

// ---------------- untokenize ----------------
__global__ void untok_kernel(float* __restrict__ out) {
    __shared__ float tile[32][33];
    int b  = blockIdx.z;
    int s0 = blockIdx.x * 32;
    int c0 = blockIdx.y * 32;
    int tx = threadIdx.x, ty = threadIdx.y;
    #pragma unroll
    for (int r = ty; r < 32; r += 8)
        tile[r][tx] = g_t[(size_t)(b * TOK + s0 + r) * CDIM + c0 + tx];
    __syncthreads();
    #pragma unroll
    for (int r = ty; r < 32; r += 8)
        out[(size_t)(b * CDIM + c0 + r) * TOK + s0 + tx] = tile[tx][r];
}

// ---------------- launch ----------------
extern "C" void kernel_launch(void* const* d_in, const int* in_sizes, int n_in,
                              void* d_out, int out_size) {
    const float* x      = (const float*)d_in[0];
    const float* pos_w  = (const float*)d_in[1];
    const float* pos_b  = (const float*)d_in[2];
    const float* ln1_w  = (const float*)d_in[3];
    const float* ln1_b  = (const float*)d_in[4];
    const float* qkv_w  = (const float*)d_in[5];
    const float* proj_w = (const float*)d_in[6];
    const float* proj_b = (const float*)d_in[7];
    const float* ln2_w  = (const float*)d_in[8];
    const float* ln2_b  = (const float*)d_in[9];
    const float* fc1_w  = (const float*)d_in[10];
    const float* fc1_b  = (const float*)d_in[11];
    const float* fc2_w  = (const float*)d_in[12];
    const float* fc2_b  = (const float*)d_in[13];
    float* out = (float*)d_out;

    float* t;
    __half *q16, *h16, *o16, *m16, *w16;
    cudaGetSymbolAddress((void**)&t,   g_t);
    cudaGetSymbolAddress((void**)&q16, g_q16);
    cudaGetSymbolAddress((void**)&h16, g_h16);
    cudaGetSymbolAddress((void**)&o16, g_o16);
    cudaGetSymbolAddress((void**)&m16, g_m16);
    cudaGetSymbolAddress((void**)&w16, g_w16);

    cudaFuncSetAttribute(gemm_h<1>, cudaFuncAttributeMaxDynamicSharedMemorySize, GHSMEM_B);
    cudaFuncSetAttribute(gemm_h<2>, cudaFuncAttributeMaxDynamicSharedMemorySize, GHSMEM_B);
    cudaFuncSetAttribute(gemm_h<3>, cudaFuncAttributeMaxDynamicSharedMemorySize, GHSMEM_B);

    cvt16<<<(QKVDIM * CDIM + 255) / 256, 256>>>(qkv_w,  w16 + W_QKV,  QKVDIM * CDIM);
    cvt16<<<(CDIM * CDIM + 255) / 256, 256>>>(proj_w,  w16 + W_PROJ, CDIM * CDIM);
    cvt16<<<(HID * CDIM + 255) / 256, 256>>>(fc1_w,    w16 + W_FC1,  HID * CDIM);
    cvt16<<<(CDIM * HID + 255) / 256, 256>>>(fc2_w,    w16 + W_FC2,  CDIM * HID);

    conv_pos_kernel<<<BATCH * CDIM, 256>>>(x, pos_w, pos_b);
    ln_kernel<<<TTOK, 256>>>(t, ln1_w, ln1_b, h16);
    gemm_h<3><<<dim3(QKVDIM / 128, TTOK / 128), 256, GHSMEM_B>>>(
        h16, w16 + W_QKV, nullptr, nullptr, nullptr, q16, QKVDIM, CDIM);
    attn_h<<<dim3(25, BATCH * NHEAD), 128>>>(q16, o16);
    gemm_h<1><<<dim3(CDIM / 128, TTOK / 128), 256, GHSMEM_B>>>(
        o16, w16 + W_PROJ, proj_b, t, t, nullptr, CDIM, CDIM);
    ln_kernel<<<TTOK, 256>>>(t, ln2_w, ln2_b, h16);
    gemm_h<2><<<dim3(HID / 128, TTOK / 128), 256, GHSMEM_B>>>(
        h16, w16 + W_FC1, fc1_b, nullptr, nullptr, m16, HID, CDIM);
    gemm_h<1><<<dim3(CDIM / 128, TTOK / 128), 256, GHSMEM_B>>>(
        m16, w16 + W_FC2, fc2_b, t, t, nullptr, CDIM, HID);
    untok_kernel<<<dim3(TOK / 32, CDIM / 32, BATCH), dim3(32, 8)>>>(out);
}

// round 11
// speedup vs baseline: 1.9620x; 1.0650x over previous
#include <cuda_runtime.h>
#include <cuda_fp16.h>
#include <math.h>
#include <stdint.h>

#define TOK    1568
#define BATCH  4
#define CDIM   768
#define TTOK   (BATCH*TOK)
#define QKVDIM 2304
#define HID    3072
#define NHEAD  12
#define DHEAD  64

#define W_QKV  0
#define W_PROJ 1769472
#define W_FC1  2359296
#define W_FC2  4718592
#define W_TOT  7077888

__device__ float  g_t[TTOK * CDIM];
__device__ __half g_q16[TTOK * QKVDIM];
__device__ __half g_h16[TTOK * CDIM];
__device__ __half g_o16[TTOK * CDIM];
__device__ __half g_m16[TTOK * HID];
__device__ __half g_w16[W_TOT];

// ---------------- ptx helpers ----------------
__device__ __forceinline__ void mma_f16(float* d, const uint32_t* a, const uint32_t* b) {
    asm volatile(
        "mma.sync.aligned.m16n8k16.row.col.f32.f16.f16.f32 "
        "{%0,%1,%2,%3}, {%4,%5,%6,%7}, {%8,%9}, {%0,%1,%2,%3};"
        : "+f"(d[0]), "+f"(d[1]), "+f"(d[2]), "+f"(d[3])
        : "r"(a[0]), "r"(a[1]), "r"(a[2]), "r"(a[3]), "r"(b[0]), "r"(b[1]));
}
__device__ __forceinline__ void ldsm4(uint32_t* r, uint32_t addr) {
    asm volatile("ldmatrix.sync.aligned.m8n8.x4.shared.b16 {%0,%1,%2,%3}, [%4];"
                 : "=r"(r[0]), "=r"(r[1]), "=r"(r[2]), "=r"(r[3]) : "r"(addr));
}
__device__ __forceinline__ void cp16(uint32_t dst, const void* src) {
    asm volatile("cp.async.cg.shared.global [%0], [%1], 16;" :: "r"(dst), "l"(src));
}
__device__ __forceinline__ void cp_commit() { asm volatile("cp.async.commit_group;"); }
template <int N> __device__ __forceinline__ void cp_wait() {
    asm volatile("cp.async.wait_group %0;" :: "n"(N));
}
__device__ __forceinline__ float gelu_exact(float v) {
    return 0.5f * v * (1.f + erff(v * 0.70710678118654752f));
}

// ---------------- fused fp32 -> fp16 weight convert ----------------
__global__ void cvtw(const float* __restrict__ qkv_w, const float* __restrict__ proj_w,
                     const float* __restrict__ fc1_w, const float* __restrict__ fc2_w,
                     __half* __restrict__ dst) {
    int i = blockIdx.x * 256 + threadIdx.x;
    float v;
    if (i < W_PROJ)      v = qkv_w[i];
    else if (i < W_FC1)  v = proj_w[i - W_PROJ];
    else if (i < W_FC2)  v = fc1_w[i - W_FC1];
    else                 v = fc2_w[i - W_FC2];
    dst[i] = __float2half(v);
}

// ---------------- conv + bias + residual + tokenize ----------------
__global__ void conv_pos_kernel(const float* __restrict__ x,
                                const float* __restrict__ pw,
                                const float* __restrict__ pb) {
    int bc = blockIdx.x;
    int c  = bc % CDIM;
    int b  = bc / CDIM;
    __shared__ float sx[TOK];
    __shared__ float sw[27];
    int tid = threadIdx.x;
    const float* xs = x + (size_t)bc * TOK;
    for (int i = tid; i < TOK; i += 256) sx[i] = xs[i];
    if (tid < 27) sw[tid] = pw[c * 27 + tid];
    __syncthreads();
    float pbv = pb[c];
    for (int idx = tid; idx < TOK; idx += 256) {
        int d = idx / 196; int r = idx - d * 196;
        int h = r / 14;    int w = r - h * 14;
        float acc = 0.f;
        #pragma unroll
        for (int kd = 0; kd < 3; kd++) {
            int dd = d + kd - 1;
            if (dd < 0 || dd >= 8) continue;
            #pragma unroll
            for (int kh = 0; kh < 3; kh++) {
                int hh = h + kh - 1;
                if (hh < 0 || hh >= 14) continue;
                #pragma unroll
                for (int kw = 0; kw < 3; kw++) {
                    int ww = w + kw - 1;
                    if (ww < 0 || ww >= 14) continue;
                    acc += sw[kd * 9 + kh * 3 + kw] * sx[dd * 196 + hh * 14 + ww];
                }
            }
        }
        g_t[(size_t)(b * TOK + idx) * CDIM + c] = sx[idx] + acc + pbv;
    }
}

// ---------------- LayerNorm -> fp16 ----------------
__global__ void ln_kernel(const float* __restrict__ in, const float* __restrict__ w,
                          const float* __restrict__ bsrc, __half* __restrict__ out) {
    int t = blockIdx.x;
    int tid = threadIdx.x;
    const float* row = in + (size_t)t * CDIM;
    float v0 = row[tid], v1 = row[tid + 256], v2 = row[tid + 512];
    float s  = v0 + v1 + v2;
    float sq = v0 * v0 + v1 * v1 + v2 * v2;
    #pragma unroll
    for (int off = 16; off; off >>= 1) {
        s  += __shfl_xor_sync(0xffffffffu, s,  off);
        sq += __shfl_xor_sync(0xffffffffu, sq, off);
    }
    __shared__ float ss[8], ssq[8];
    int wid = tid >> 5, lid = tid & 31;
    if (lid == 0) { ss[wid] = s; ssq[wid] = sq; }
    __syncthreads();
    if (tid < 32) {
        s  = (lid < 8) ? ss[lid]  : 0.f;
        sq = (lid < 8) ? ssq[lid] : 0.f;
        #pragma unroll
        for (int off = 4; off; off >>= 1) {
            s  += __shfl_xor_sync(0xffffffffu, s,  off);
            sq += __shfl_xor_sync(0xffffffffu, sq, off);
        }
        if (lid == 0) { ss[0] = s; ssq[0] = sq; }
    }
    __syncthreads();
    float mean = ss[0] * (1.f / CDIM);
    float var  = ssq[0] * (1.f / CDIM) - mean * mean;
    float rs   = rsqrtf(var + 1e-5f);
    __half* orow = out + (size_t)t * CDIM;
    orow[tid]       = __float2half((v0 - mean) * rs * w[tid]       + bsrc[tid]);
    orow[tid + 256] = __float2half((v1 - mean) * rs * w[tid + 256] + bsrc[tid + 256]);
    orow[tid + 512] = __float2half((v2 - mean) * rs * w[tid + 512] + bsrc[tid + 512]);
}

// ---------------- fp16 mma GEMM with ldmatrix fragments ----------------
// MODE 0: Cf=acc ; 1: Cf=acc+bias+resid ; 2: Ch=gelu(acc+bias) ; 3: Ch=acc
// Smem rows: 32 halves + 8 pad = 40 halves (80 B). ldmatrix banks 20r%32: conflict-free.
#define GH_STRIDE 20
#define GH_MATW   (128 * GH_STRIDE)
#define GH_STAGEW (2 * GH_MATW)
#define GHSMEM_B  (3 * GH_STAGEW * 4)

template <int MODE>
__global__ void __launch_bounds__(256, 2)
gemm_h(const __half* __restrict__ A, const __half* __restrict__ B,
       const float* __restrict__ bias, const float* __restrict__ resid,
       float* __restrict__ Cf, __half* __restrict__ Ch, int N, int K) {
    extern __shared__ __align__(16) uint32_t smw[];
    int tid = threadIdx.x;
    int lane = tid & 31, warp = tid >> 5;
    int wm = warp >> 2, wn = warp & 3;
    int m0 = blockIdx.y << 7, n0 = blockIdx.x << 7;
    uint32_t smbase = (uint32_t)__cvta_generic_to_shared(smw);

    int lrow = tid >> 1;
    int lpart = tid & 1;
    const __half* Ag = A + (size_t)(m0 + lrow) * K + lpart * 16;
    const __half* Bg = B + (size_t)(n0 + lrow) * K + lpart * 16;
    uint32_t sa0 = smbase + (lrow * GH_STRIDE + lpart * 8) * 4;
    uint32_t sb0 = sa0 + GH_MATW * 4;

    int nch = K >> 5;
    auto load_chunk = [&](int ch) {
        uint32_t d = (uint32_t)(ch % 3) * (GH_STAGEW * 4);
        int off = ch << 5;
        cp16(sa0 + d, Ag + off); cp16(sa0 + d + 16, Ag + off + 8);
        cp16(sb0 + d, Bg + off); cp16(sb0 + d + 16, Bg + off + 8);
        cp_commit();
    };

    float acc[4][4][4];
    #pragma unroll
    for (int mi = 0; mi < 4; mi++)
        #pragma unroll
        for (int ni = 0; ni < 4; ni++)
            #pragma unroll
            for (int r = 0; r < 4; r++) acc[mi][ni][r] = 0.f;

    // ldmatrix per-thread addresses
    int grp = lane >> 3, trow = lane & 7;
    int arow = ((grp & 1) << 3) + trow, acol = (grp >> 1) << 3;  // A: grp1->row+8, grp2->col+8
    int brow = ((grp >> 1) << 3) + trow, bcol = (grp & 1) << 3;  // B: grp1->col+8, grp2->row+8
    uint32_t aaddr[4], baddr[2];
    #pragma unroll
    for (int mi = 0; mi < 4; mi++)
        aaddr[mi] = smbase + ((wm * 64 + mi * 16 + arow) * 40 + acol) * 2;
    #pragma unroll
    for (int np = 0; np < 2; np++)
        baddr[np] = smbase + GH_MATW * 4 + ((wn * 32 + np * 16 + brow) * 40 + bcol) * 2;

    load_chunk(0);
    load_chunk(1);
    for (int ch = 0; ch < nch; ch++) {
        if (ch < nch - 1) cp_wait<1>(); else cp_wait<0>();
        __syncthreads();
        if (ch + 2 < nch) load_chunk(ch + 2);
        uint32_t soff = (uint32_t)(ch % 3) * (GH_STAGEW * 4);
        #pragma unroll
        for (int kt = 0; kt < 2; kt++) {
            uint32_t koff = soff + kt * 32;
            uint32_t af[4][4], bfr[2][4];
            #pragma unroll
            for (int mi = 0; mi < 4; mi++) ldsm4(af[mi], aaddr[mi] + koff);
            #pragma unroll
            for (int np = 0; np < 2; np++) ldsm4(bfr[np], baddr[np] + koff);
            #pragma unroll
            for (int mi = 0; mi < 4; mi++)
                #pragma unroll
                for (int ni = 0; ni < 4; ni++)
                    mma_f16(acc[mi][ni], af[mi], &bfr[ni >> 1][(ni & 1) * 2]);
        }
    }

    int r0 = lane >> 2, cq = (lane & 3) * 2;
    #pragma unroll
    for (int mi = 0; mi < 4; mi++) {
        int rowA = m0 + wm * 64 + mi * 16 + r0;
        int rowB = rowA + 8;
        #pragma unroll
        for (int ni = 0; ni < 4; ni++) {
            int col = n0 + wn * 32 + ni * 8 + cq;
            float2 va = make_float2(acc[mi][ni][0], acc[mi][ni][1]);
            float2 vb = make_float2(acc[mi][ni][2], acc[mi][ni][3]);
            if (MODE == 0) {
                *(float2*)(Cf + (size_t)rowA * N + col) = va;
                *(float2*)(Cf + (size_t)rowB * N + col) = vb;
            } else if (MODE == 1) {
                float2 bv = *(const float2*)(bias + col);
                float2 ra = *(const float2*)(resid + (size_t)rowA * N + col);
                float2 rb = *(const float2*)(resid + (size_t)rowB * N + col);
                va.x += bv.x + ra.x; va.y += bv.y + ra.y;
                vb.x += bv.x + rb.x; vb.y += bv.y + rb.y;
                *(float2*)(Cf + (size_t)rowA * N + col) = va;
                *(float2*)(Cf + (size_t)rowB * N + col) = vb;
            } else if (MODE == 2) {
                float2 bv = *(const float2*)(bias + col);
                va.x = gelu_exact(va.x + bv.x); va.y = gelu_exact(va.y + bv.y);
                vb.x = gelu_exact(vb.x + bv.x); vb.y = gelu_exact(vb.y + bv.y);
                *(__half2*)(Ch + (size_t)rowA * N + col) = __floats2half2_rn(va.x, va.y);
                *(__half2*)(Ch + (size_t)rowB * N + col) = __floats2half2_rn(vb.x, vb.y);
            } else {
                *(__half2*)(Ch + (size_t)rowA * N + col) = __floats2half2_rn(va.x, va.y);
                *(__half2*)(Ch + (size_t)rowB * N + col) = __floats2half2_rn(vb.x, vb.y);
            }
        }
    }
}

// ---------------- fp16 flash attention with ldmatrix fragments ----------------
// K/P stride 72 halves (144 B, banks 4r%32 conflict-free); V transposed Vt[d][key].
__global__ void __launch_bounds__(128)
attn_h(const __half* __restrict__ qkv, __half* __restrict__ o) {
    __shared__ __align__(16) __half Ks[64 * 72];
    __shared__ __align__(16) __half Vt[64 * 72];
    __shared__ __align__(16) __half Ps[64 * 72];
    int tid = threadIdx.x, lane = tid & 31, warp = tid >> 5;
    int bh = blockIdx.y;
    int b = bh / NHEAD, h = bh % NHEAD;
    int q0 = blockIdx.x * 64;
    const __half* base = qkv + (size_t)b * TOK * QKVDIM + h * DHEAD;

    int r0 = lane >> 2, kq = lane & 3;
    int qa = q0 + warp * 16 + r0;
    int qb = qa + 8;
    bool va = qa < TOK, vb = qb < TOK;

    uint32_t qf[4][4];
    {
        const __half2 sc = __floats2half2_rn(0.125f, 0.125f);
        const __half* pa = base + (size_t)qa * QKVDIM;
        const __half* pb = base + (size_t)qb * QKVDIM;
        #pragma unroll
        for (int kt = 0; kt < 4; kt++) {
            int k = kt * 16 + 2 * kq;
            __half2 v;
            v = va ? __hmul2(*(const __half2*)(pa + k), sc) : __floats2half2_rn(0.f, 0.f);
            qf[kt][0] = *(uint32_t*)&v;
            v = vb ? __hmul2(*(const __half2*)(pb + k), sc) : __floats2half2_rn(0.f, 0.f);
            qf[kt][1] = *(uint32_t*)&v;
            v = va ? __hmul2(*(const __half2*)(pa + k + 8), sc) : __floats2half2_rn(0.f, 0.f);
            qf[kt][2] = *(uint32_t*)&v;
            v = vb ? __hmul2(*(const __half2*)(pb + k + 8), sc) : __floats2half2_rn(0.f, 0.f);
            qf[kt][3] = *(uint32_t*)&v;
        }
    }

    // ldmatrix addresses
    int grp = lane >> 3, trow = lane & 7;
    int arow = ((grp & 1) << 3) + trow, acol = (grp >> 1) << 3;
    int brow = ((grp >> 1) << 3) + trow, bcol = (grp & 1) << 3;
    uint32_t ksm = (uint32_t)__cvta_generic_to_shared(Ks);
    uint32_t vsm = (uint32_t)__cvta_generic_to_shared(Vt);
    uint32_t psm = (uint32_t)__cvta_generic_to_shared(Ps);
    uint32_t kaddr[4], vaddr[4], paddr;
    #pragma unroll
    for (int np = 0; np < 4; np++) {
        kaddr[np] = ksm + ((np * 16 + brow) * 72 + bcol) * 2;
        vaddr[np] = vsm + ((np * 16 + brow) * 72 + bcol) * 2;
    }
    paddr = psm + ((warp * 16 + arow) * 72 + acol) * 2;

    float oacc[8][4];
    #pragma unroll
    for (int nt = 0; nt < 8; nt++)
        #pragma unroll
        for (int rr = 0; rr < 4; rr++) oacc[nt][rr] = 0.f;
    float mi0 = -1e30f, mi1 = -1e30f, li0 = 0.f, li1 = 0.f;
    int prow = warp * 16 + r0;

    for (int kc = 0; kc < 25; kc++) {
        __syncthreads();
        #pragma unroll
        for (int i = 0; i < 4; i++) {
            int g = tid + i * 128;
            int row = g >> 3, c8 = (g & 7) << 3;
            int kg = kc * 64 + row;
            uint4 v = make_uint4(0u, 0u, 0u, 0u);
            if (kg < TOK) v = *(const uint4*)(base + (size_t)kg * QKVDIM + CDIM + c8);
            *(uint4*)&Ks[row * 72 + c8] = v;
        }
        #pragma unroll
        for (int i = 0; i < 2; i++) {
            int g = tid + i * 128;
            int kp = g >> 3, dg = (g & 7) << 3;
            int k0 = kc * 64 + 2 * kp;
            uint4 a = make_uint4(0u, 0u, 0u, 0u), bq = make_uint4(0u, 0u, 0u, 0u);
            if (k0 < TOK)     a  = *(const uint4*)(base + (size_t)k0 * QKVDIM + 2 * CDIM + dg);
            if (k0 + 1 < TOK) bq = *(const uint4*)(base + (size_t)(k0 + 1) * QKVDIM + 2 * CDIM + dg);
            const __half* ah = (const __half*)&a;
            const __half* bh2 = (const __half*)&bq;
            #pragma unroll
            for (int j = 0; j < 8; j++) {
                __half2 p; p.x = ah[j]; p.y = bh2[j];
                *(__half2*)&Vt[(dg + j) * 72 + 2 * kp] = p;
            }
        }
        __syncthreads();

        // S = Q K^T
        float s[8][4];
        #pragma unroll
        for (int ni = 0; ni < 8; ni++)
            #pragma unroll
            for (int rr = 0; rr < 4; rr++) s[ni][rr] = 0.f;
        #pragma unroll
        for (int kt = 0; kt < 4; kt++) {
            uint32_t koff = kt * 32;
            #pragma unroll
            for (int np = 0; np < 4; np++) {
                uint32_t bb[4];
                ldsm4(bb, kaddr[np] + koff);
                mma_f16(s[2 * np],     qf[kt], bb);
                mma_f16(s[2 * np + 1], qf[kt], bb + 2);
            }
        }
        if (kc == 24) {
            #pragma unroll
            for (int ni = 0; ni < 8; ni++) {
                int c = kc * 64 + ni * 8 + kq * 2;
                if (c >= TOK)     { s[ni][0] = -1e30f; s[ni][2] = -1e30f; }
                if (c + 1 >= TOK) { s[ni][1] = -1e30f; s[ni][3] = -1e30f; }
            }
        }
        float mr0 = -1e30f, mr1 = -1e30f;
        #pragma unroll
        for (int ni = 0; ni < 8; ni++) {
            mr0 = fmaxf(mr0, fmaxf(s[ni][0], s[ni][1]));
            mr1 = fmaxf(mr1, fmaxf(s[ni][2], s[ni][3]));
        }
        mr0 = fmaxf(mr0, __shfl_xor_sync(0xffffffffu, mr0, 1));
        mr0 = fmaxf(mr0, __shfl_xor_sync(0xffffffffu, mr0, 2));
        mr1 = fmaxf(mr1, __shfl_xor_sync(0xffffffffu, mr1, 1));
        mr1 = fmaxf(mr1, __shfl_xor_sync(0xffffffffu, mr1, 2));
        float mn0 = fmaxf(mi0, mr0), mn1 = fmaxf(mi1, mr1);
        float a0 = __expf(mi0 - mn0), a1 = __expf(mi1 - mn1);
        float sum0 = 0.f, sum1 = 0.f;
        #pragma unroll
        for (int ni = 0; ni < 8; ni++) {
            s[ni][0] = __expf(s[ni][0] - mn0);
            s[ni][1] = __expf(s[ni][1] - mn0);
            s[ni][2] = __expf(s[ni][2] - mn1);
            s[ni][3] = __expf(s[ni][3] - mn1);
            sum0 += s[ni][0] + s[ni][1];
            sum1 += s[ni][2] + s[ni][3];
        }
        sum0 += __shfl_xor_sync(0xffffffffu, sum0, 1);
        sum0 += __shfl_xor_sync(0xffffffffu, sum0, 2);
        sum1 += __shfl_xor_sync(0xffffffffu, sum1, 1);
        sum1 += __shfl_xor_sync(0xffffffffu, sum1, 2);
        li0 = li0 * a0 + sum0; li1 = li1 * a1 + sum1;
        mi0 = mn0; mi1 = mn1;
        #pragma unroll
        for (int nt = 0; nt < 8; nt++) {
            oacc[nt][0] *= a0; oacc[nt][1] *= a0;
            oacc[nt][2] *= a1; oacc[nt][3] *= a1;
        }
        #pragma unroll
        for (int ni = 0; ni < 8; ni++) {
            int col = ni * 8 + kq * 2;
            *(__half2*)&Ps[prow * 72 + col]       = __floats2half2_rn(s[ni][0], s[ni][1]);
            *(__half2*)&Ps[(prow + 8) * 72 + col] = __floats2half2_rn(s[ni][2], s[ni][3]);
        }
        __syncwarp();
        // O += P V
        #pragma unroll
        for (int kt = 0; kt < 4; kt++) {
            uint32_t koff = kt * 32;
            uint32_t pf[4];
            ldsm4(pf, paddr + koff);
            #pragma unroll
            for (int np = 0; np < 4; np++) {
                uint32_t bb[4];
                ldsm4(bb, vaddr[np] + koff);
                mma_f16(oacc[2 * np],     pf, bb);
                mma_f16(oacc[2 * np + 1], pf, bb + 2);
            }
        }
    }

    float inv0 = 1.f / li0, inv1 = 1.f / li1;
    #pragma unroll
    for (int nt = 0; nt < 8; nt++) {
        int col = h * DHEAD + nt * 8 + kq * 2;
        if (va)
            *(__half2*)(o + (size_t)(b * TOK + qa) * CDIM + col) =
                __floats2half2_rn(oacc[nt][0] * inv0, oacc[nt][1] * inv0);
        if (vb)
            *(__half2*)(o + (size_t)(b * TOK + qb) * CDIM + col) =
                __floats2half2_rn(oacc[nt][2] * inv1, oacc[nt][3] * inv1);
    }
}

// ---------------- untokenize ----------------
__global__ void untok_kernel(float* __restrict__ out) {
    __shared__ float tile[32][33];
    int b  = blockIdx.z;
    int s0 = blockIdx.x * 32;
    int c0 = blockIdx.y * 32;
    int tx = threadIdx.x, ty = threadIdx.y;
    #pragma unroll
    for (int r = ty; r < 32; r += 8)
        tile[r][tx] = g_t[(size_t)(b * TOK + s0 + r) * CDIM + c0 + tx];
    __syncthreads();
    #pragma unroll
    for (int r = ty; r < 32; r += 8)
        out[(size_t)(b * CDIM + c0 + r) * TOK + s0 + tx] = tile[tx][r];
}

// ---------------- launch ----------------
extern "C" void kernel_launch(void* const* d_in, const int* in_sizes, int n_in,
                              void* d_out, int out_size) {
    const float* x      = (const float*)d_in[0];
    const float* pos_w  = (const float*)d_in[1];
    const float* pos_b  = (const float*)d_in[2];
    const float* ln1_w  = (const float*)d_in[3];
    const float* ln1_b  = (const float*)d_in[4];
    const float* qkv_w  = (const float*)d_in[5];
    const float* proj_w = (const float*)d_in[6];
    const float* proj_b = (const float*)d_in[7];
    const float* ln2_w  = (const float*)d_in[8];
    const float* ln2_b  = (const float*)d_in[9];
    const float* fc1_w  = (const float*)d_in[10];
    const float* fc1_b  = (const float*)d_in[11];
    const float* fc2_w  = (const float*)d_in[12];
    const float* fc2_b  = (const float*)d_in[13];
    float* out = (float*)d_out;

    float* t;
    __half *q16, *h16, *o16, *m16, *w16;
    cudaGetSymbolAddress((void**)&t,   g_t);
    cudaGetSymbolAddress((void**)&q16, g_q16);
    cudaGetSymbolAddress((void**)&h16, g_h16);
    cudaGetSymbolAddress((void**)&o16, g_o16);
    cudaGetSymbolAddress((void**)&m16, g_m16);
    cudaGetSymbolAddress((void**)&w16, g_w16);

    cudaFuncSetAttribute(gemm_h<1>, cudaFuncAttributeMaxDynamicSharedMemorySize, GHSMEM_B);
    cudaFuncSetAttribute(gemm_h<2>, cudaFuncAttributeMaxDynamicSharedMemorySize, GHSMEM_B);
    cudaFuncSetAttribute(gemm_h<3>, cudaFuncAttributeMaxDynamicSharedMemorySize, GHSMEM_B);

    cvtw<<<W_TOT / 256, 256>>>(qkv_w, proj_w, fc1_w, fc2_w, w16);
    conv_pos_kernel<<<BATCH * CDIM, 256>>>(x, pos_w, pos_b);
    ln_kernel<<<TTOK, 256>>>(t, ln1_w, ln1_b, h16);
    gemm_h<3><<<dim3(QKVDIM / 128, TTOK / 128), 256, GHSMEM_B>>>(
        h16, w16 + W_QKV, nullptr, nullptr, nullptr, q16, QKVDIM, CDIM);
    attn_h<<<dim3(25, BATCH * NHEAD), 128>>>(q16, o16);
    gemm_h<1><<<dim3(CDIM / 128, TTOK / 128), 256, GHSMEM_B>>>(
        o16, w16 + W_PROJ, proj_b, t, t, nullptr, CDIM, CDIM);
    ln_kernel<<<TTOK, 256>>>(t, ln2_w, ln2_b, h16);
    gemm_h<2><<<dim3(HID / 128, TTOK / 128), 256, GHSMEM_B>>>(
        h16, w16 + W_FC1, fc1_b, nullptr, nullptr, m16, HID, CDIM);
    gemm_h<1><<<dim3(CDIM / 128, TTOK / 128), 256, GHSMEM_B>>>(
        m16, w16 + W_FC2, fc2_b, t, t, nullptr, CDIM, HID);
    untok_kernel<<<dim3(TOK / 32, CDIM / 32, BATCH), dim3(32, 8)>>>(out);
}

// round 13
// speedup vs baseline: 2.1242x; 1.0827x over previous
#include <cuda_runtime.h>
#include <cuda_fp16.h>
#include <math.h>
#include <stdint.h>

#define TOK    1568
#define BATCH  4
#define CDIM   768
#define TTOK   (BATCH*TOK)
#define QKVDIM 2304
#define HID    3072
#define NHEAD  12
#define DHEAD  64

#define W_QKV  0
#define W_PROJ 1769472
#define W_FC1  2359296
#define W_FC2  4718592
#define W_TOT  7077888

__device__ float  g_t[TTOK * CDIM];
__device__ __half g_q16[TTOK * QKVDIM];
__device__ __half g_h16[TTOK * CDIM];
__device__ __half g_o16[TTOK * CDIM];
__device__ __half g_m16[TTOK * HID];
__device__ __half g_w16[W_TOT];

// ---------------- ptx helpers ----------------
__device__ __forceinline__ void mma_f16(float* d, const uint32_t* a, const uint32_t* b) {
    asm volatile(
        "mma.sync.aligned.m16n8k16.row.col.f32.f16.f16.f32 "
        "{%0,%1,%2,%3}, {%4,%5,%6,%7}, {%8,%9}, {%0,%1,%2,%3};"
        : "+f"(d[0]), "+f"(d[1]), "+f"(d[2]), "+f"(d[3])
        : "r"(a[0]), "r"(a[1]), "r"(a[2]), "r"(a[3]), "r"(b[0]), "r"(b[1]));
}
__device__ __forceinline__ void ldsm4(uint32_t* r, uint32_t addr) {
    asm volatile("ldmatrix.sync.aligned.m8n8.x4.shared.b16 {%0,%1,%2,%3}, [%4];"
                 : "=r"(r[0]), "=r"(r[1]), "=r"(r[2]), "=r"(r[3]) : "r"(addr));
}
__device__ __forceinline__ void ldsm4t(uint32_t* r, uint32_t addr) {
    asm volatile("ldmatrix.sync.aligned.m8n8.x4.trans.shared.b16 {%0,%1,%2,%3}, [%4];"
                 : "=r"(r[0]), "=r"(r[1]), "=r"(r[2]), "=r"(r[3]) : "r"(addr));
}
__device__ __forceinline__ void cp16(uint32_t dst, const void* src) {
    asm volatile("cp.async.cg.shared.global [%0], [%1], 16;" :: "r"(dst), "l"(src));
}
__device__ __forceinline__ void cp_commit() { asm volatile("cp.async.commit_group;"); }
template <int N> __device__ __forceinline__ void cp_wait() {
    asm volatile("cp.async.wait_group %0;" :: "n"(N));
}
__device__ __forceinline__ float gelu_exact(float v) {
    return 0.5f * v * (1.f + erff(v * 0.70710678118654752f));
}

// ---------------- fused fp32 -> fp16 weight convert ----------------
__global__ void cvtw(const float* __restrict__ qkv_w, const float* __restrict__ proj_w,
                     const float* __restrict__ fc1_w, const float* __restrict__ fc2_w,
                     __half* __restrict__ dst) {
    int i = blockIdx.x * 256 + threadIdx.x;
    float v;
    if (i < W_PROJ)      v = qkv_w[i];
    else if (i < W_FC1)  v = proj_w[i - W_PROJ];
    else if (i < W_FC2)  v = fc1_w[i - W_FC1];
    else                 v = fc2_w[i - W_FC2];
    dst[i] = __float2half(v);
}

// ---------------- conv + bias + residual + tokenize ----------------
__global__ void conv_pos_kernel(const float* __restrict__ x,
                                const float* __restrict__ pw,
                                const float* __restrict__ pb) {
    int bc = blockIdx.x;
    int c  = bc % CDIM;
    int b  = bc / CDIM;
    __shared__ float sx[TOK];
    __shared__ float sw[27];
    int tid = threadIdx.x;
    const float* xs = x + (size_t)bc * TOK;
    for (int i = tid; i < TOK; i += 256) sx[i] = xs[i];
    if (tid < 27) sw[tid] = pw[c * 27 + tid];
    __syncthreads();
    float pbv = pb[c];
    for (int idx = tid; idx < TOK; idx += 256) {
        int d = idx / 196; int r = idx - d * 196;
        int h = r / 14;    int w = r - h * 14;
        float acc = 0.f;
        #pragma unroll
        for (int kd = 0; kd < 3; kd++) {
            int dd = d + kd - 1;
            if (dd < 0 || dd >= 8) continue;
            #pragma unroll
            for (int kh = 0; kh < 3; kh++) {
                int hh = h + kh - 1;
                if (hh < 0 || hh >= 14) continue;
                #pragma unroll
                for (int kw = 0; kw < 3; kw++) {
                    int ww = w + kw - 1;
                    if (ww < 0 || ww >= 14) continue;
                    acc += sw[kd * 9 + kh * 3 + kw] * sx[dd * 196 + hh * 14 + ww];
                }
            }
        }
        g_t[(size_t)(b * TOK + idx) * CDIM + c] = sx[idx] + acc + pbv;
    }
}

// ---------------- LayerNorm -> fp16 ----------------
__global__ void ln_kernel(const float* __restrict__ in, const float* __restrict__ w,
                          const float* __restrict__ bsrc, __half* __restrict__ out) {
    int t = blockIdx.x;
    int tid = threadIdx.x;
    const float* row = in + (size_t)t * CDIM;
    float v0 = row[tid], v1 = row[tid + 256], v2 = row[tid + 512];
    float s  = v0 + v1 + v2;
    float sq = v0 * v0 + v1 * v1 + v2 * v2;
    #pragma unroll
    for (int off = 16; off; off >>= 1) {
        s  += __shfl_xor_sync(0xffffffffu, s,  off);
        sq += __shfl_xor_sync(0xffffffffu, sq, off);
    }
    __shared__ float ss[8], ssq[8];
    int wid = tid >> 5, lid = tid & 31;
    if (lid == 0) { ss[wid] = s; ssq[wid] = sq; }
    __syncthreads();
    if (tid < 32) {
        s  = (lid < 8) ? ss[lid]  : 0.f;
        sq = (lid < 8) ? ssq[lid] : 0.f;
        #pragma unroll
        for (int off = 4; off; off >>= 1) {
            s  += __shfl_xor_sync(0xffffffffu, s,  off);
            sq += __shfl_xor_sync(0xffffffffu, sq, off);
        }
        if (lid == 0) { ss[0] = s; ssq[0] = sq; }
    }
    __syncthreads();
    float mean = ss[0] * (1.f / CDIM);
    float var  = ssq[0] * (1.f / CDIM) - mean * mean;
    float rs   = rsqrtf(var + 1e-5f);
    __half* orow = out + (size_t)t * CDIM;
    orow[tid]       = __float2half((v0 - mean) * rs * w[tid]       + bsrc[tid]);
    orow[tid + 256] = __float2half((v1 - mean) * rs * w[tid + 256] + bsrc[tid + 256]);
    orow[tid + 512] = __float2half((v2 - mean) * rs * w[tid + 512] + bsrc[tid + 512]);
}

// ---------------- fp16 mma GEMM, ldmatrix fragments, 4-stage cp.async ----------------
#define GH_STRIDE 20
#define GH_MATW   (128 * GH_STRIDE)
#define GH_STAGEW (2 * GH_MATW)
#define GHSMEM_B  (4 * GH_STAGEW * 4)   // 81920 bytes

template <int MODE>
__global__ void __launch_bounds__(256, 2)
gemm_h(const __half* __restrict__ A, const __half* __restrict__ B,
       const float* __restrict__ bias, const float* __restrict__ resid,
       float* __restrict__ Cf, __half* __restrict__ Ch, int N, int K) {
    extern __shared__ __align__(16) uint32_t smw[];
    int tid = threadIdx.x;
    int lane = tid & 31, warp = tid >> 5;
    int wm = warp >> 2, wn = warp & 3;
    int m0 = blockIdx.y << 7, n0 = blockIdx.x << 7;
    uint32_t smbase = (uint32_t)__cvta_generic_to_shared(smw);

    int lrow = tid >> 1;
    int lpart = tid & 1;
    const __half* Ag = A + (size_t)(m0 + lrow) * K + lpart * 16;
    const __half* Bg = B + (size_t)(n0 + lrow) * K + lpart * 16;
    uint32_t sa0 = smbase + (lrow * GH_STRIDE + lpart * 8) * 4;
    uint32_t sb0 = sa0 + GH_MATW * 4;

    int nch = K >> 5;
    auto load_chunk = [&](int ch) {
        uint32_t d = (uint32_t)(ch & 3) * (GH_STAGEW * 4);
        int off = ch << 5;
        cp16(sa0 + d, Ag + off); cp16(sa0 + d + 16, Ag + off + 8);
        cp16(sb0 + d, Bg + off); cp16(sb0 + d + 16, Bg + off + 8);
        cp_commit();
    };

    float acc[4][4][4];
    #pragma unroll
    for (int mi = 0; mi < 4; mi++)
        #pragma unroll
        for (int ni = 0; ni < 4; ni++)
            #pragma unroll
            for (int r = 0; r < 4; r++) acc[mi][ni][r] = 0.f;

    int grp = lane >> 3, trow = lane & 7;
    int arow = ((grp & 1) << 3) + trow, acol = (grp >> 1) << 3;
    int brow = ((grp >> 1) << 3) + trow, bcol = (grp & 1) << 3;
    uint32_t aaddr[4], baddr[2];
    #pragma unroll
    for (int mi = 0; mi < 4; mi++)
        aaddr[mi] = smbase + ((wm * 64 + mi * 16 + arow) * 40 + acol) * 2;
    #pragma unroll
    for (int np = 0; np < 2; np++)
        baddr[np] = smbase + GH_MATW * 4 + ((wn * 32 + np * 16 + brow) * 40 + bcol) * 2;

    load_chunk(0);
    load_chunk(1);
    load_chunk(2);
    for (int ch = 0; ch < nch; ch++) {
        if (ch + 3 <= nch - 1)      cp_wait<2>();
        else if (ch + 2 <= nch - 1) cp_wait<1>();
        else                        cp_wait<0>();
        __syncthreads();
        if (ch + 3 < nch) load_chunk(ch + 3);
        uint32_t soff = (uint32_t)(ch & 3) * (GH_STAGEW * 4);
        #pragma unroll
        for (int kt = 0; kt < 2; kt++) {
            uint32_t koff = soff + kt * 32;
            uint32_t af[4][4], bfr[2][4];
            #pragma unroll
            for (int mi = 0; mi < 4; mi++) ldsm4(af[mi], aaddr[mi] + koff);
            #pragma unroll
            for (int np = 0; np < 2; np++) ldsm4(bfr[np], baddr[np] + koff);
            #pragma unroll
            for (int mi = 0; mi < 4; mi++)
                #pragma unroll
                for (int ni = 0; ni < 4; ni++)
                    mma_f16(acc[mi][ni], af[mi], &bfr[ni >> 1][(ni & 1) * 2]);
        }
    }

    int r0 = lane >> 2, cq = (lane & 3) * 2;
    #pragma unroll
    for (int mi = 0; mi < 4; mi++) {
        int rowA = m0 + wm * 64 + mi * 16 + r0;
        int rowB = rowA + 8;
        #pragma unroll
        for (int ni = 0; ni < 4; ni++) {
            int col = n0 + wn * 32 + ni * 8 + cq;
            float2 va = make_float2(acc[mi][ni][0], acc[mi][ni][1]);
            float2 vb = make_float2(acc[mi][ni][2], acc[mi][ni][3]);
            if (MODE == 0) {
                *(float2*)(Cf + (size_t)rowA * N + col) = va;
                *(float2*)(Cf + (size_t)rowB * N + col) = vb;
            } else if (MODE == 1) {
                float2 bv = *(const float2*)(bias + col);
                float2 ra = *(const float2*)(resid + (size_t)rowA * N + col);
                float2 rb = *(const float2*)(resid + (size_t)rowB * N + col);
                va.x += bv.x + ra.x; va.y += bv.y + ra.y;
                vb.x += bv.x + rb.x; vb.y += bv.y + rb.y;
                *(float2*)(Cf + (size_t)rowA * N + col) = va;
                *(float2*)(Cf + (size_t)rowB * N + col) = vb;
            } else if (MODE == 2) {
                float2 bv = *(const float2*)(bias + col);
                va.x = gelu_exact(va.x + bv.x); va.y = gelu_exact(va.y + bv.y);
                vb.x = gelu_exact(vb.x + bv.x); vb.y = gelu_exact(vb.y + bv.y);
                *(__half2*)(Ch + (size_t)rowA * N + col) = __floats2half2_rn(va.x, va.y);
                *(__half2*)(Ch + (size_t)rowB * N + col) = __floats2half2_rn(vb.x, vb.y);
            } else {
                *(__half2*)(Ch + (size_t)rowA * N + col) = __floats2half2_rn(va.x, va.y);
                *(__half2*)(Ch + (size_t)rowB * N + col) = __floats2half2_rn(vb.x, vb.y);
            }
        }
    }
}

// ---------------- fp16 flash attention: cp.async double-buffered K/V, trans-V ----------------
__global__ void __launch_bounds__(128)
attn_h(const __half* __restrict__ qkv, __half* __restrict__ o) {
    __shared__ __align__(16) __half Ks[2][64 * 72];
    __shared__ __align__(16) __half Vs[2][64 * 72];
    __shared__ __align__(16) __half Ps[64 * 72];
    int tid = threadIdx.x, lane = tid & 31, warp = tid >> 5;
    int bh = blockIdx.y;
    int b = bh / NHEAD, h = bh % NHEAD;
    int q0 = blockIdx.x * 64;
    const __half* base = qkv + (size_t)b * TOK * QKVDIM + h * DHEAD;

    int r0 = lane >> 2, kq = lane & 3;
    int qa = q0 + warp * 16 + r0;
    int qb = qa + 8;
    bool va = qa < TOK, vb = qb < TOK;

    uint32_t qf[4][4];
    {
        const __half2 sc = __floats2half2_rn(0.125f, 0.125f);
        const __half* pa = base + (size_t)qa * QKVDIM;
        const __half* pb = base + (size_t)qb * QKVDIM;
        #pragma unroll
        for (int kt = 0; kt < 4; kt++) {
            int k = kt * 16 + 2 * kq;
            __half2 v;
            v = va ? __hmul2(*(const __half2*)(pa + k), sc) : __floats2half2_rn(0.f, 0.f);
            qf[kt][0] = *(uint32_t*)&v;
            v = vb ? __hmul2(*(const __half2*)(pb + k), sc) : __floats2half2_rn(0.f, 0.f);
            qf[kt][1] = *(uint32_t*)&v;
            v = va ? __hmul2(*(const __half2*)(pa + k + 8), sc) : __floats2half2_rn(0.f, 0.f);
            qf[kt][2] = *(uint32_t*)&v;
            v = vb ? __hmul2(*(const __half2*)(pb + k + 8), sc) : __floats2half2_rn(0.f, 0.f);
            qf[kt][3] = *(uint32_t*)&v;
        }
    }

    uint32_t ksm = (uint32_t)__cvta_generic_to_shared(Ks);
    uint32_t vsm = (uint32_t)__cvta_generic_to_shared(Vs);
    uint32_t psm = (uint32_t)__cvta_generic_to_shared(Ps);
    const uint32_t KVBUF = 64 * 72 * 2;   // 9216 B

    int ldrow = tid >> 3, ldc8 = (tid & 7) << 3;
    auto loadKV = [&](int kc, int st) {
        uint32_t kb = ksm + st * KVBUF;
        uint32_t vbuf = vsm + st * KVBUF;
        #pragma unroll
        for (int i = 0; i < 4; i++) {
            int row = ldrow + i * 16;
            int kg = kc * 64 + row;
            if (kg > TOK - 1) kg = TOK - 1;
            const __half* src = base + (size_t)kg * QKVDIM;
            uint32_t doff = (row * 72 + ldc8) * 2;
            cp16(kb + doff,   src + CDIM + ldc8);
            cp16(vbuf + doff, src + 2 * CDIM + ldc8);
        }
        cp_commit();
    };

    int grp = lane >> 3, trow = lane & 7;
    int arow = ((grp & 1) << 3) + trow, acol = (grp >> 1) << 3;   // P (A, non-trans)
    int brow = ((grp >> 1) << 3) + trow, bcol = (grp & 1) << 3;   // K (B, non-trans)
    int vrow = ((grp & 1) << 3) + trow,  vcol = (grp >> 1) << 3;  // V (B, trans)
    uint32_t koff_[4], voff_[4], paddr;
    #pragma unroll
    for (int np = 0; np < 4; np++) {
        koff_[np] = ((np * 16 + brow) * 72 + bcol) * 2;
        voff_[np] = (vrow * 72 + np * 16 + vcol) * 2;
    }
    paddr = psm + ((warp * 16 + arow) * 72 + acol) * 2;

    float oacc[8][4];
    #pragma unroll
    for (int nt = 0; nt < 8; nt++)
        #pragma unroll
        for (int rr = 0; rr < 4; rr++) oacc[nt][rr] = 0.f;
    float mi0 = -1e30f, mi1 = -1e30f, li0 = 0.f, li1 = 0.f;
    int prow = warp * 16 + r0;

    loadKV(0, 0);
    for (int kc = 0; kc < 25; kc++) {
        cp_wait<0>();
        __syncthreads();
        if (kc + 1 < 25) loadKV(kc + 1, (kc + 1) & 1);
        uint32_t kb = ksm + (kc & 1) * KVBUF;
        uint32_t vbuf = vsm + (kc & 1) * KVBUF;

        float s[8][4];
        #pragma unroll
        for (int ni = 0; ni < 8; ni++)
            #pragma unroll
            for (int rr = 0; rr < 4; rr++) s[ni][rr] = 0.f;
        #pragma unroll
        for (int kt = 0; kt < 4; kt++) {
            uint32_t koff = kt * 32;
            #pragma unroll
            for (int np = 0; np < 4; np++) {
                uint32_t bb[4];
                ldsm4(bb, kb + koff_[np] + koff);
                mma_f16(s[2 * np],     qf[kt], bb);
                mma_f16(s[2 * np + 1], qf[kt], bb + 2);
            }
        }
        if (kc == 24) {
            #pragma unroll
            for (int ni = 0; ni < 8; ni++) {
                int c = kc * 64 + ni * 8 + kq * 2;
                if (c >= TOK)     { s[ni][0] = -1e30f; s[ni][2] = -1e30f; }
                if (c + 1 >= TOK) { s[ni][1] = -1e30f; s[ni][3] = -1e30f; }
            }
        }
        float mr0 = -1e30f, mr1 = -1e30f;
        #pragma unroll
        for (int ni = 0; ni < 8; ni++) {
            mr0 = fmaxf(mr0, fmaxf(s[ni][0], s[ni][1]));
            mr1 = fmaxf(mr1, fmaxf(s[ni][2], s[ni][3]));
        }
        mr0 = fmaxf(mr0, __shfl_xor_sync(0xffffffffu, mr0, 1));
        mr0 = fmaxf(mr0, __shfl_xor_sync(0xffffffffu, mr0, 2));
        mr1 = fmaxf(mr1, __shfl_xor_sync(0xffffffffu, mr1, 1));
        mr1 = fmaxf(mr1, __shfl_xor_sync(0xffffffffu, mr1, 2));
        float mn0 = fmaxf(mi0, mr0), mn1 = fmaxf(mi1, mr1);
        float a0 = __expf(mi0 - mn0), a1 = __expf(mi1 - mn1);
        float sum0 = 0.f, sum1 = 0.f;
        #pragma unroll
        for (int ni = 0; ni < 8; ni++) {
            s[ni][0] = __expf(s[ni][0] - mn0);
            s[ni][1] = __expf(s[ni][1] - mn0);
            s[ni][2] = __expf(s[ni][2] - mn1);
            s[ni][3] = __expf(s[ni][3] - mn1);
            sum0 += s[ni][0] + s[ni][1];
            sum1 += s[ni][2] + s[ni][3];
        }
        sum0 += __shfl_xor_sync(0xffffffffu, sum0, 1);
        sum0 += __shfl_xor_sync(0xffffffffu, sum0, 2);
        sum1 += __shfl_xor_sync(0xffffffffu, sum1, 1);
        sum1 += __shfl_xor_sync(0xffffffffu, sum1, 2);
        li0 = li0 * a0 + sum0; li1 = li1 * a1 + sum1;
        mi0 = mn0; mi1 = mn1;
        #pragma unroll
        for (int nt = 0; nt < 8; nt++) {
            oacc[nt][0] *= a0; oacc[nt][1] *= a0;
            oacc[nt][2] *= a1; oacc[nt][3] *= a1;
        }
        #pragma unroll
        for (int ni = 0; ni < 8; ni++) {
            int col = ni * 8 + kq * 2;
            *(__half2*)&Ps[prow * 72 + col]       = __floats2half2_rn(s[ni][0], s[ni][1]);
            *(__half2*)&Ps[(prow + 8) * 72 + col] = __floats2half2_rn(s[ni][2], s[ni][3]);
        }
        __syncwarp();
        #pragma unroll
        for (int kt = 0; kt < 4; kt++) {
            uint32_t pf[4];
            ldsm4(pf, paddr + kt * 32);
            uint32_t vko = kt * 16 * 72 * 2;
            #pragma unroll
            for (int np = 0; np < 4; np++) {
                uint32_t bb[4];
                ldsm4t(bb, vbuf + voff_[np] + vko);
                mma_f16(oacc[2 * np],     pf, bb);
                mma_f16(oacc[2 * np + 1], pf, bb + 2);
            }
        }
    }

    float inv0 = 1.f / li0, inv1 = 1.f / li1;
    #pragma unroll
    for (int nt = 0; nt < 8; nt++) {
        int col = h * DHEAD + nt * 8 + kq * 2;
        if (va)
            *(__half2*)(o + (size_t)(b * TOK + qa) * CDIM + col) =
                __floats2half2_rn(oacc[nt][0] * inv0, oacc[nt][1] * inv0);
        if (vb)
            *(__half2*)(o + (size_t)(b * TOK + qb) * CDIM + col) =
                __floats2half2_rn(oacc[nt][2] * inv1, oacc[nt][3] * inv1);
    }
}

// ---------------- untokenize ----------------
__global__ void untok_kernel(float* __restrict__ out) {
    __shared__ float tile[32][33];
    int b  = blockIdx.z;
    int s0 = blockIdx.x * 32;
    int c0 = blockIdx.y * 32;
    int tx = threadIdx.x, ty = threadIdx.y;
    #pragma unroll
    for (int r = ty; r < 32; r += 8)
        tile[r][tx] = g_t[(size_t)(b * TOK + s0 + r) * CDIM + c0 + tx];
    __syncthreads();
    #pragma unroll
    for (int r = ty; r < 32; r += 8)
        out[(size_t)(b * CDIM + c0 + r) * TOK + s0 + tx] = tile[tx][r];
}

// ---------------- launch ----------------
extern "C" void kernel_launch(void* const* d_in, const int* in_sizes, int n_in,
                              void* d_out, int out_size) {
    const float* x      = (const float*)d_in[0];
    const float* pos_w  = (const float*)d_in[1];
    const float* pos_b  = (const float*)d_in[2];
    const float* ln1_w  = (const float*)d_in[3];
    const float* ln1_b  = (const float*)d_in[4];
    const float* qkv_w  = (const float*)d_in[5];
    const float* proj_w = (const float*)d_in[6];
    const float* proj_b = (const float*)d_in[7];
    const float* ln2_w  = (const float*)d_in[8];
    const float* ln2_b  = (const float*)d_in[9];
    const float* fc1_w  = (const float*)d_in[10];
    const float* fc1_b  = (const float*)d_in[11];
    const float* fc2_w  = (const float*)d_in[12];
    const float* fc2_b  = (const float*)d_in[13];
    float* out = (float*)d_out;

    float* t;
    __half *q16, *h16, *o16, *m16, *w16;
    cudaGetSymbolAddress((void**)&t,   g_t);
    cudaGetSymbolAddress((void**)&q16, g_q16);
    cudaGetSymbolAddress((void**)&h16, g_h16);
    cudaGetSymbolAddress((void**)&o16, g_o16);
    cudaGetSymbolAddress((void**)&m16, g_m16);
    cudaGetSymbolAddress((void**)&w16, g_w16);

    cudaFuncSetAttribute(gemm_h<1>, cudaFuncAttributeMaxDynamicSharedMemorySize, GHSMEM_B);
    cudaFuncSetAttribute(gemm_h<2>, cudaFuncAttributeMaxDynamicSharedMemorySize, GHSMEM_B);
    cudaFuncSetAttribute(gemm_h<3>, cudaFuncAttributeMaxDynamicSharedMemorySize, GHSMEM_B);

    cvtw<<<W_TOT / 256, 256>>>(qkv_w, proj_w, fc1_w, fc2_w, w16);
    conv_pos_kernel<<<BATCH * CDIM, 256>>>(x, pos_w, pos_b);
    ln_kernel<<<TTOK, 256>>>(t, ln1_w, ln1_b, h16);
    gemm_h<3><<<dim3(QKVDIM / 128, TTOK / 128), 256, GHSMEM_B>>>(
        h16, w16 + W_QKV, nullptr, nullptr, nullptr, q16, QKVDIM, CDIM);
    attn_h<<<dim3(25, BATCH * NHEAD), 128>>>(q16, o16);
    gemm_h<1><<<dim3(CDIM / 128, TTOK / 128), 256, GHSMEM_B>>>(
        o16, w16 + W_PROJ, proj_b, t, t, nullptr, CDIM, CDIM);
    ln_kernel<<<TTOK, 256>>>(t, ln2_w, ln2_b, h16);
    gemm_h<2><<<dim3(HID / 128, TTOK / 128), 256, GHSMEM_B>>>(
        h16, w16 + W_FC1, fc1_b, nullptr, nullptr, m16, HID, CDIM);
    gemm_h<1><<<dim3(CDIM / 128, TTOK / 128), 256, GHSMEM_B>>>(
        m16, w16 + W_FC2, fc2_b, t, t, nullptr, CDIM, HID);
    untok_kernel<<<dim3(TOK / 32, CDIM / 32, BATCH), dim3(32, 8)>>>(out);
}